// round 11
// baseline (speedup 1.0000x reference)
#include <cuda_runtime.h>
#include <cuda_fp16.h>
#include <cstdint>
#include <math.h>

// Shapes fixed by dataset: x:(4,2048,1024) f32, pad:(4,2048) i32,
// w*:(1024,1024) f32, b*:(1024) f32, h=16 (depth 64). out:(4,2048,1024) f32.
static const int Bb = 4;
static const int Nn = 2048;
static const int Dd = 1024;
static const int Mm = Bb * Nn; // 8192

// Scratch (no allocs allowed) — everything pre-split into fp16 hi/lo pairs.
__device__ __half g_Xh[8192 * 1024];
__device__ __half g_Xl[8192 * 1024];
__device__ __half g_Qh[8192 * 1024];
__device__ __half g_Ql[8192 * 1024];
__device__ __half g_Kh[8192 * 1024];
__device__ __half g_Kl[8192 * 1024];
__device__ __half g_Vh[8192 * 1024];
__device__ __half g_Vl[8192 * 1024];
__device__ __half g_Oh[8192 * 1024];
__device__ __half g_Ol[8192 * 1024];
__device__ __half g_WTh[4 * 1024 * 1024];
__device__ __half g_WTl[4 * 1024 * 1024];

// ---------------------------------------------------------------------------
// Helpers (sm_80-era PTX: mma.sync + ldmatrix + cp.async)
// ---------------------------------------------------------------------------
__device__ __forceinline__ uint32_t smem_u32(const void* p) {
    uint32_t a;
    asm("{ .reg .u64 t; cvta.to.shared.u64 t, %1; cvt.u32.u64 %0, t; }"
        : "=r"(a) : "l"(p));
    return a;
}
__device__ __forceinline__ void ldm4(uint32_t* q, uint32_t addr) {
    asm volatile("ldmatrix.sync.aligned.m8n8.x4.shared.b16 {%0,%1,%2,%3}, [%4];"
                 : "=r"(q[0]), "=r"(q[1]), "=r"(q[2]), "=r"(q[3]) : "r"(addr));
}
__device__ __forceinline__ void ldm4t(uint32_t* q, uint32_t addr) {
    asm volatile("ldmatrix.sync.aligned.m8n8.x4.trans.shared.b16 {%0,%1,%2,%3}, [%4];"
                 : "=r"(q[0]), "=r"(q[1]), "=r"(q[2]), "=r"(q[3]) : "r"(addr));
}
__device__ __forceinline__ void mma_f16(float* c, const uint32_t* a,
                                        uint32_t b0, uint32_t b1) {
    asm("mma.sync.aligned.m16n8k16.row.col.f32.f16.f16.f32 "
        "{%0,%1,%2,%3}, {%4,%5,%6,%7}, {%8,%9}, {%0,%1,%2,%3};"
        : "+f"(c[0]), "+f"(c[1]), "+f"(c[2]), "+f"(c[3])
        : "r"(a[0]), "r"(a[1]), "r"(a[2]), "r"(a[3]), "r"(b0), "r"(b1));
}
__device__ __forceinline__ void cp_async16(uint32_t dst, const void* src) {
    asm volatile("cp.async.cg.shared.global [%0], [%1], 16;"
                 :: "r"(dst), "l"(src) : "memory");
}
__device__ __forceinline__ void cp_commit() {
    asm volatile("cp.async.commit_group;" ::: "memory");
}
template <int N> __device__ __forceinline__ void cp_wait() {
    asm volatile("cp.async.wait_group %0;" :: "n"(N) : "memory");
}
__device__ __forceinline__ uint32_t pack2h(__half a, __half b) {
    __half2 t;
    t.x = a; t.y = b;
    return *reinterpret_cast<uint32_t*>(&t);
}
// Exact split: v = hi + lo (both fp16), elementwise.
__device__ __forceinline__ void split4h(float4 v, uint2& hi, uint2& lo) {
    __half hx = __float2half_rn(v.x);
    __half hy = __float2half_rn(v.y);
    __half hz = __float2half_rn(v.z);
    __half hw = __float2half_rn(v.w);
    hi = make_uint2(pack2h(hx, hy), pack2h(hz, hw));
    lo = make_uint2(
        pack2h(__float2half_rn(v.x - __half2float(hx)),
               __float2half_rn(v.y - __half2float(hy))),
        pack2h(__float2half_rn(v.z - __half2float(hz)),
               __float2half_rn(v.w - __half2float(hw))));
}

// ---------------------------------------------------------------------------
// One-time converters
// ---------------------------------------------------------------------------
__global__ __launch_bounds__(256) void split_f32_kernel(
    const float* __restrict__ in, __half* __restrict__ oh,
    __half* __restrict__ ol, int n4)
{
    int id = blockIdx.x * 256 + threadIdx.x;
    if (id < n4) {
        float4 v = ((const float4*)in)[id];
        uint2 hi, lo;
        split4h(v, hi, lo);
        ((uint2*)oh)[id] = hi;
        ((uint2*)ol)[id] = lo;
    }
}

// Transpose + split: WT[n][k] = W[k][n], written as fp16 hi/lo.
__global__ __launch_bounds__(256) void transpose_split_k(
    const float* __restrict__ in, __half* __restrict__ oh,
    __half* __restrict__ ol)
{
    __shared__ float t[32][33];
    int x = blockIdx.x * 32 + threadIdx.x;
    int y = blockIdx.y * 32 + threadIdx.y;
#pragma unroll
    for (int j = 0; j < 32; j += 8)
        t[threadIdx.y + j][threadIdx.x] = in[(size_t)(y + j) * 1024 + x];
    __syncthreads();
    int xo = blockIdx.y * 32 + threadIdx.x;
    int yo = blockIdx.x * 32 + threadIdx.y;
#pragma unroll
    for (int j = 0; j < 32; j += 8) {
        float v = t[threadIdx.x][threadIdx.y + j];
        __half hv = __float2half_rn(v);
        oh[(size_t)(yo + j) * 1024 + xo] = hv;
        ol[(size_t)(yo + j) * 1024 + xo] = __float2half_rn(v - __half2float(hv));
    }
}

// ---------------------------------------------------------------------------
// fp16 3-term GEMM on pre-split inputs:
//   C = Ah@Bh + Ah@Bl + Al@Bh + bias, all scaled by `scale`.
// Staging = pure cp.async 16B copies (no conversion); 1 sync per chunk.
// OUT16: write (hi,lo) fp16 pair; else write f32.
// ---------------------------------------------------------------------------
static const int PANEL = 2080;               // 128 rows * 16B + 32 pad
static const int BUFSZ = 16 * PANEL;         // Ah,Al,Bh,Bl x 4 panels
static const int GEMM_SMEM = 2 * BUFSZ;      // 66560

template <bool OUT16>
__global__ __launch_bounds__(256) void gemm_f16x3_kernel(
    const __half* __restrict__ Ah, const __half* __restrict__ Al,
    const __half* __restrict__ Bh, const __half* __restrict__ Bl,
    const float* __restrict__ bias, float scale,
    float* __restrict__ Cf, __half* __restrict__ Ch, __half* __restrict__ Cl)
{
    extern __shared__ __align__(16) char smem[];
    const uint32_t sbase = smem_u32(smem);
    const int tid = threadIdx.x;
    const int wid = tid >> 5;
    const int lane = tid & 31;
    const int wm = (wid >> 1) * 32;
    const int wn = (wid & 1) * 64;
    const int brow = blockIdx.y * 128;
    const int bcol = blockIdx.x * 128;

    const __half* srcs[4] = {Ah + (size_t)brow * 1024, Al + (size_t)brow * 1024,
                             Bh + (size_t)bcol * 1024, Bl + (size_t)bcol * 1024};

    float c[2][8][4];
#pragma unroll
    for (int mt = 0; mt < 2; ++mt)
#pragma unroll
        for (int nt = 0; nt < 8; ++nt)
#pragma unroll
            for (int i = 0; i < 4; ++i) c[mt][nt][i] = 0.0f;

    auto stage = [&](int ch) {
        const uint32_t bb = sbase + (ch & 1) * BUFSZ;
        const int kbase = ch * 32;
#pragma unroll
        for (int i = 0; i < 8; ++i) {
            int id = tid + i * 256;
            int part = id >> 9;        // 0 Ah, 1 Al, 2 Bh, 3 Bl
            int idx = id & 511;
            int row = idx >> 2;        // 0..127
            int g = idx & 3;           // k8-group within chunk
            cp_async16(bb + part * (4 * PANEL) + g * PANEL + row * 16,
                       srcs[part] + (size_t)row * 1024 + kbase + g * 8);
        }
    };

    stage(0);
    cp_commit();

    for (int ch = 0; ch < 32; ++ch) {
        cp_wait<0>();
        __syncthreads();
        if (ch + 1 < 32) { stage(ch + 1); cp_commit(); }

        const uint32_t bb = sbase + (ch & 1) * BUFSZ;
#pragma unroll
        for (int ks = 0; ks < 2; ++ks) {
            const int g0 = ks * 2;
            uint32_t Afh[2][4], Afl[2][4];       // [gg][quad]
            uint32_t Bfh[2][2][4], Bfl[2][2][4]; // [gg][ng][quad]
#pragma unroll
            for (int gg = 0; gg < 2; ++gg) {
                uint32_t arow = bb + (g0 + gg) * PANEL + (wm + lane) * 16;
                ldm4(Afh[gg], arow);
                ldm4(Afl[gg], arow + 4 * PANEL);
#pragma unroll
                for (int ng = 0; ng < 2; ++ng) {
                    uint32_t brow_ = bb + (g0 + gg) * PANEL +
                                     (wn + ng * 32 + lane) * 16;
                    ldm4(Bfh[gg][ng], brow_ + 8 * PANEL);
                    ldm4(Bfl[gg][ng], brow_ + 12 * PANEL);
                }
            }
            uint32_t ah[2][4], al[2][4];
#pragma unroll
            for (int mt = 0; mt < 2; ++mt) {
                ah[mt][0] = Afh[0][mt * 2]; ah[mt][1] = Afh[0][mt * 2 + 1];
                ah[mt][2] = Afh[1][mt * 2]; ah[mt][3] = Afh[1][mt * 2 + 1];
                al[mt][0] = Afl[0][mt * 2]; al[mt][1] = Afl[0][mt * 2 + 1];
                al[mt][2] = Afl[1][mt * 2]; al[mt][3] = Afl[1][mt * 2 + 1];
            }
            // term-major: 3 sweeps of 16 independent mmas
#pragma unroll
            for (int mt = 0; mt < 2; ++mt)
#pragma unroll
                for (int nt = 0; nt < 8; ++nt)
                    mma_f16(c[mt][nt], ah[mt],
                            Bfh[0][nt >> 2][nt & 3], Bfh[1][nt >> 2][nt & 3]);
#pragma unroll
            for (int mt = 0; mt < 2; ++mt)
#pragma unroll
                for (int nt = 0; nt < 8; ++nt)
                    mma_f16(c[mt][nt], ah[mt],
                            Bfl[0][nt >> 2][nt & 3], Bfl[1][nt >> 2][nt & 3]);
#pragma unroll
            for (int mt = 0; mt < 2; ++mt)
#pragma unroll
                for (int nt = 0; nt < 8; ++nt)
                    mma_f16(c[mt][nt], al[mt],
                            Bfh[0][nt >> 2][nt & 3], Bfh[1][nt >> 2][nt & 3]);
        }
        __syncthreads();
    }

    const int r0b = brow + wm + (lane >> 2);
    const int colb = bcol + wn + 2 * (lane & 3);
#pragma unroll
    for (int mt = 0; mt < 2; ++mt) {
#pragma unroll
        for (int nt = 0; nt < 8; ++nt) {
            const int col = colb + nt * 8;
            const float2 bi = *(const float2*)(bias + col);
            const int r0 = r0b + mt * 16;
            float v0 = (c[mt][nt][0] + bi.x) * scale;
            float v1 = (c[mt][nt][1] + bi.y) * scale;
            float v2 = (c[mt][nt][2] + bi.x) * scale;
            float v3 = (c[mt][nt][3] + bi.y) * scale;
            if (OUT16) {
                __half h0 = __float2half_rn(v0), h1 = __float2half_rn(v1);
                __half h2 = __float2half_rn(v2), h3 = __float2half_rn(v3);
                *(uint32_t*)(Ch + (size_t)r0 * 1024 + col) = pack2h(h0, h1);
                *(uint32_t*)(Cl + (size_t)r0 * 1024 + col) =
                    pack2h(__float2half_rn(v0 - __half2float(h0)),
                           __float2half_rn(v1 - __half2float(h1)));
                *(uint32_t*)(Ch + (size_t)(r0 + 8) * 1024 + col) = pack2h(h2, h3);
                *(uint32_t*)(Cl + (size_t)(r0 + 8) * 1024 + col) =
                    pack2h(__float2half_rn(v2 - __half2float(h2)),
                           __float2half_rn(v3 - __half2float(h3)));
            } else {
                *(float2*)(Cf + (size_t)r0 * 1024 + col) = make_float2(v0, v1);
                *(float2*)(Cf + (size_t)(r0 + 8) * 1024 + col) = make_float2(v2, v3);
            }
        }
    }
}

// ---------------------------------------------------------------------------
// Tensor-core flash attention, fp16 3-term, on PRE-SPLIT hi/lo inputs.
// Staging = pure cp.async copies. Math identical to R10 (rel_err 2.3e-4).
// Writes O as fp16 hi/lo pair for the final projection.
// ---------------------------------------------------------------------------
static const int QPNL = 2080;
static const int KPNL = 1056;
static const int VSTR = 144;
static const int SQHI = 0;
static const int SQLO = 8 * QPNL;             // 16640
static const int SKHI = 16 * QPNL;            // 33280
static const int SKLO = SKHI + 8 * KPNL;      // 41728
static const int SVHI = SKLO + 8 * KPNL;      // 50176
static const int SVLO = SVHI + 64 * VSTR;     // 59392
static const int SAM  = SVLO + 64 * VSTR;     // 68608
static const int ATTN_SMEM = SAM + 64 * 4;    // 68864

__global__ __launch_bounds__(256) void attn_mma_kernel(
    const __half* __restrict__ Qh, const __half* __restrict__ Ql,
    const __half* __restrict__ Kh, const __half* __restrict__ Kl,
    const __half* __restrict__ Vh, const __half* __restrict__ Vl,
    const int* __restrict__ pad,
    __half* __restrict__ Oh, __half* __restrict__ Ol)
{
    extern __shared__ __align__(16) char smem[];
    const uint32_t sb = smem_u32(smem);
    const int tid = threadIdx.x;
    const int wid = tid >> 5;
    const int lane = tid & 31;
    const int wm = wid * 16;
    const int bh = blockIdx.y;
    const int b = bh >> 4;
    const int h = bh & 15;
    const int qbase = blockIdx.x * 128;

    const size_t bhoff = (size_t)b * Nn * 1024 + h * 64;
    const __half* Qhp = Qh + bhoff;
    const __half* Qlp = Ql + bhoff;
    const __half* kvsrcs[4] = {Kh + bhoff, Kl + bhoff, Vh + bhoff, Vl + bhoff};

    // ---- stage Q tile (already scaled & split) via cp.async ----
#pragma unroll
    for (int i = 0; i < 8; ++i) {
        int id = tid + i * 256;
        int part = id >> 10;      // 0 Qh, 1 Ql
        int idx = id & 1023;
        int row = idx >> 3;       // 0..127
        int g = idx & 7;          // k8-group (depth)
        const __half* src = (part ? Qlp : Qhp) + (size_t)(qbase + row) * 1024 + g * 8;
        cp_async16(sb + (part ? SQLO : SQHI) + g * QPNL + row * 16, src);
    }
    cp_commit();
    cp_wait<0>();
    __syncthreads();

    uint32_t qh[4][4], ql[4][4];
#pragma unroll
    for (int kc = 0; kc < 4; ++kc) {
        uint32_t addr = sb + SQHI + (2 * kc + (lane >> 4)) * QPNL +
                        (wm + (lane & 15)) * 16;
        ldm4(qh[kc], addr);
        ldm4(ql[kc], addr + (SQLO - SQHI));
    }

    const int r = lane >> 2;
    const int qn0 = qbase + wm + r;
    const int qn1 = qn0 + 8;
    const float vn0 = (pad[b * Nn + qn0] == 0) ? 1.0f : 0.0f;
    const float vn1 = (pad[b * Nn + qn1] == 0) ? 1.0f : 0.0f;

    float o[8][4];
#pragma unroll
    for (int nd = 0; nd < 8; ++nd)
#pragma unroll
        for (int i = 0; i < 4; ++i) o[nd][i] = 0.0f;
    float m0 = -1e30f, m1 = -1e30f, l0 = 0.0f, l1 = 0.0f;

    for (int kt = 0; kt < Nn; kt += 64) {
        __syncthreads();   // prior tile fully consumed before overwrite
        // ---- stage K (hi/lo panels) + V (hi/lo rows) via cp.async ----
#pragma unroll
        for (int i = 0; i < 8; ++i) {
            int id = tid + i * 256;
            int part = id >> 9;      // 0 Kh, 1 Kl, 2 Vh, 3 Vl
            int idx = id & 511;
            int row = idx >> 3;      // 0..63
            int g = idx & 7;
            const __half* src = kvsrcs[part] + (size_t)(kt + row) * 1024 + g * 8;
            uint32_t dst;
            if (part < 2)
                dst = sb + (part ? SKLO : SKHI) + g * KPNL + row * 16;
            else
                dst = sb + (part == 2 ? SVHI : SVLO) + row * VSTR + g * 16;
            cp_async16(dst, src);
        }
        cp_commit();
        if (tid < 64)
            *(float*)(smem + SAM + tid * 4) =
                (pad[b * Nn + kt + tid] == 0) ? 1.0f : 0.0f;
        cp_wait<0>();
        __syncthreads();

        // ---- S = qh Kh + qh Kl + ql Kh ----
        float s[8][4];
#pragma unroll
        for (int nt = 0; nt < 8; ++nt)
#pragma unroll
            for (int i = 0; i < 4; ++i) s[nt][i] = 0.0f;

#pragma unroll
        for (int kc = 0; kc < 4; ++kc) {
            uint32_t b0h[4], b4h[4], b1h[4], b5h[4];
            uint32_t b0l[4], b4l[4], b1l[4], b5l[4];
            uint32_t p0 = sb + SKHI + (2 * kc) * KPNL + lane * 16;
            uint32_t p1 = sb + SKHI + (2 * kc + 1) * KPNL + lane * 16;
            ldm4(b0h, p0);
            ldm4(b4h, p0 + 32 * 16);
            ldm4(b1h, p1);
            ldm4(b5h, p1 + 32 * 16);
            ldm4(b0l, p0 + (SKLO - SKHI));
            ldm4(b4l, p0 + 32 * 16 + (SKLO - SKHI));
            ldm4(b1l, p1 + (SKLO - SKHI));
            ldm4(b5l, p1 + 32 * 16 + (SKLO - SKHI));
#pragma unroll
            for (int nt = 0; nt < 8; ++nt)
                mma_f16(s[nt], qh[kc],
                        (nt < 4) ? b0h[nt] : b4h[nt - 4],
                        (nt < 4) ? b1h[nt] : b5h[nt - 4]);
#pragma unroll
            for (int nt = 0; nt < 8; ++nt)
                mma_f16(s[nt], qh[kc],
                        (nt < 4) ? b0l[nt] : b4l[nt - 4],
                        (nt < 4) ? b1l[nt] : b5l[nt - 4]);
#pragma unroll
            for (int nt = 0; nt < 8; ++nt)
                mma_f16(s[nt], ql[kc],
                        (nt < 4) ? b0h[nt] : b4h[nt - 4],
                        (nt < 4) ? b1h[nt] : b5h[nt - 4]);
        }

        // ---- mask (exact-zero form) + online softmax ----
        float tm0 = -1e30f, tm1 = -1e30f;
#pragma unroll
        for (int nt = 0; nt < 8; ++nt) {
            float2 vm = *(const float2*)(smem + SAM +
                                         (nt * 8 + 2 * (lane & 3)) * 4);
            s[nt][0] = fmaf(1.0f - vn0 * vm.x, -1e6f, s[nt][0]);
            s[nt][1] = fmaf(1.0f - vn0 * vm.y, -1e6f, s[nt][1]);
            s[nt][2] = fmaf(1.0f - vn1 * vm.x, -1e6f, s[nt][2]);
            s[nt][3] = fmaf(1.0f - vn1 * vm.y, -1e6f, s[nt][3]);
            tm0 = fmaxf(tm0, fmaxf(s[nt][0], s[nt][1]));
            tm1 = fmaxf(tm1, fmaxf(s[nt][2], s[nt][3]));
        }
        tm0 = fmaxf(tm0, __shfl_xor_sync(0xffffffffu, tm0, 1));
        tm0 = fmaxf(tm0, __shfl_xor_sync(0xffffffffu, tm0, 2));
        tm1 = fmaxf(tm1, __shfl_xor_sync(0xffffffffu, tm1, 1));
        tm1 = fmaxf(tm1, __shfl_xor_sync(0xffffffffu, tm1, 2));

        float m0n = fmaxf(m0, tm0), m1n = fmaxf(m1, tm1);
        float a0 = __expf(m0 - m0n), a1 = __expf(m1 - m1n);
        m0 = m0n; m1 = m1n;

        float sum0 = 0.0f, sum1 = 0.0f;
#pragma unroll
        for (int nt = 0; nt < 8; ++nt) {
            s[nt][0] = __expf(s[nt][0] - m0);
            s[nt][1] = __expf(s[nt][1] - m0);
            s[nt][2] = __expf(s[nt][2] - m1);
            s[nt][3] = __expf(s[nt][3] - m1);
            sum0 += s[nt][0] + s[nt][1];
            sum1 += s[nt][2] + s[nt][3];
        }
        sum0 += __shfl_xor_sync(0xffffffffu, sum0, 1);
        sum0 += __shfl_xor_sync(0xffffffffu, sum0, 2);
        sum1 += __shfl_xor_sync(0xffffffffu, sum1, 1);
        sum1 += __shfl_xor_sync(0xffffffffu, sum1, 2);
        l0 = l0 * a0 + sum0;
        l1 = l1 * a1 + sum1;
#pragma unroll
        for (int nd = 0; nd < 8; ++nd) {
            o[nd][0] *= a0; o[nd][1] *= a0;
            o[nd][2] *= a1; o[nd][3] *= a1;
        }

        // ---- O += Ph Vh + Ph Vl + Pl Vh ----
#pragma unroll
        for (int kc = 0; kc < 4; ++kc) {
            uint32_t ph[4], pl[4];
            {
                const float* pa = s[2 * kc];
                const float* pb = s[2 * kc + 1];
                __half h0 = __float2half_rn(pa[0]);
                __half h1 = __float2half_rn(pa[1]);
                __half h2 = __float2half_rn(pa[2]);
                __half h3 = __float2half_rn(pa[3]);
                __half h4 = __float2half_rn(pb[0]);
                __half h5 = __float2half_rn(pb[1]);
                __half h6 = __float2half_rn(pb[2]);
                __half h7 = __float2half_rn(pb[3]);
                ph[0] = pack2h(h0, h1);
                ph[1] = pack2h(h2, h3);
                ph[2] = pack2h(h4, h5);
                ph[3] = pack2h(h6, h7);
                pl[0] = pack2h(__float2half_rn(pa[0] - __half2float(h0)),
                               __float2half_rn(pa[1] - __half2float(h1)));
                pl[1] = pack2h(__float2half_rn(pa[2] - __half2float(h2)),
                               __float2half_rn(pa[3] - __half2float(h3)));
                pl[2] = pack2h(__float2half_rn(pb[0] - __half2float(h4)),
                               __float2half_rn(pb[1] - __half2float(h5)));
                pl[3] = pack2h(__float2half_rn(pb[2] - __half2float(h6)),
                               __float2half_rn(pb[3] - __half2float(h7)));
            }
            uint32_t vh[4][4], vl[4][4];
#pragma unroll
            for (int jj = 0; jj < 4; ++jj) {
                uint32_t va = sb + SVHI + (kc * 16 + (lane & 15)) * VSTR +
                              (2 * jj + (lane >> 4)) * 16;
                ldm4t(vh[jj], va);
                ldm4t(vl[jj], va + (SVLO - SVHI));
            }
#pragma unroll
            for (int jj = 0; jj < 4; ++jj) {
                mma_f16(o[2 * jj], ph, vh[jj][0], vh[jj][1]);
                mma_f16(o[2 * jj + 1], ph, vh[jj][2], vh[jj][3]);
            }
#pragma unroll
            for (int jj = 0; jj < 4; ++jj) {
                mma_f16(o[2 * jj], ph, vl[jj][0], vl[jj][1]);
                mma_f16(o[2 * jj + 1], ph, vl[jj][2], vl[jj][3]);
            }
#pragma unroll
            for (int jj = 0; jj < 4; ++jj) {
                mma_f16(o[2 * jj], pl, vh[jj][0], vh[jj][1]);
                mma_f16(o[2 * jj + 1], pl, vh[jj][2], vh[jj][3]);
            }
        }
    }

    // ---- epilogue: O /= l, write fp16 hi/lo ----
    const float inv0 = 1.0f / l0, inv1 = 1.0f / l1;
    const size_t row0 = (size_t)(b * Nn + qn0) * 1024;
    const size_t row1 = (size_t)(b * Nn + qn1) * 1024;
#pragma unroll
    for (int nd = 0; nd < 8; ++nd) {
        const int col = h * 64 + nd * 8 + 2 * (lane & 3);
        float v0 = o[nd][0] * inv0, v1 = o[nd][1] * inv0;
        float v2 = o[nd][2] * inv1, v3 = o[nd][3] * inv1;
        __half h0 = __float2half_rn(v0), h1 = __float2half_rn(v1);
        __half h2 = __float2half_rn(v2), h3 = __float2half_rn(v3);
        *(uint32_t*)(Oh + row0 + col) = pack2h(h0, h1);
        *(uint32_t*)(Ol + row0 + col) =
            pack2h(__float2half_rn(v0 - __half2float(h0)),
                   __float2half_rn(v1 - __half2float(h1)));
        *(uint32_t*)(Oh + row1 + col) = pack2h(h2, h3);
        *(uint32_t*)(Ol + row1 + col) =
            pack2h(__float2half_rn(v2 - __half2float(h2)),
                   __float2half_rn(v3 - __half2float(h3)));
    }
}

// ---------------------------------------------------------------------------
// Launch
// ---------------------------------------------------------------------------
extern "C" void kernel_launch(void* const* d_in, const int* in_sizes, int n_in,
                              void* d_out, int out_size)
{
    const float* x  = (const float*)d_in[0];
    const int*   pd = (const int*)d_in[1];
    const float* wq = (const float*)d_in[2];
    const float* bq = (const float*)d_in[3];
    const float* wk = (const float*)d_in[4];
    const float* bk = (const float*)d_in[5];
    const float* wv = (const float*)d_in[6];
    const float* bv = (const float*)d_in[7];
    const float* wo = (const float*)d_in[8];
    const float* bo = (const float*)d_in[9];
    float* out = (float*)d_out;

    __half *Xh, *Xl, *Qh, *Ql, *Kh, *Kl, *Vh, *Vl, *Oh, *Ol, *WTh, *WTl;
    cudaGetSymbolAddress((void**)&Xh, g_Xh);
    cudaGetSymbolAddress((void**)&Xl, g_Xl);
    cudaGetSymbolAddress((void**)&Qh, g_Qh);
    cudaGetSymbolAddress((void**)&Ql, g_Ql);
    cudaGetSymbolAddress((void**)&Kh, g_Kh);
    cudaGetSymbolAddress((void**)&Kl, g_Kl);
    cudaGetSymbolAddress((void**)&Vh, g_Vh);
    cudaGetSymbolAddress((void**)&Vl, g_Vl);
    cudaGetSymbolAddress((void**)&Oh, g_Oh);
    cudaGetSymbolAddress((void**)&Ol, g_Ol);
    cudaGetSymbolAddress((void**)&WTh, g_WTh);
    cudaGetSymbolAddress((void**)&WTl, g_WTl);

    cudaFuncSetAttribute(gemm_f16x3_kernel<true>,
                         cudaFuncAttributeMaxDynamicSharedMemorySize, GEMM_SMEM);
    cudaFuncSetAttribute(gemm_f16x3_kernel<false>,
                         cudaFuncAttributeMaxDynamicSharedMemorySize, GEMM_SMEM);
    cudaFuncSetAttribute(attn_mma_kernel,
                         cudaFuncAttributeMaxDynamicSharedMemorySize, ATTN_SMEM);

    // One-time converts
    split_f32_kernel<<<(Mm * Dd / 4 + 255) / 256, 256>>>(x, Xh, Xl, Mm * Dd / 4);
    dim3 tgrid(32, 32), tblk(32, 8);
    transpose_split_k<<<tgrid, tblk>>>(wq, WTh + 0 * 1048576, WTl + 0 * 1048576);
    transpose_split_k<<<tgrid, tblk>>>(wk, WTh + 1 * 1048576, WTl + 1 * 1048576);
    transpose_split_k<<<tgrid, tblk>>>(wv, WTh + 2 * 1048576, WTl + 2 * 1048576);
    transpose_split_k<<<tgrid, tblk>>>(wo, WTh + 3 * 1048576, WTl + 3 * 1048576);

    dim3 ggrid(Dd / 128, Mm / 128); // (8, 64)
    // Q projection: fold 1/sqrt(64)=0.125 into the (x@wq+bq) result.
    gemm_f16x3_kernel<true><<<ggrid, 256, GEMM_SMEM>>>(
        Xh, Xl, WTh + 0 * 1048576, WTl + 0 * 1048576, bq, 0.125f,
        nullptr, Qh, Ql);
    gemm_f16x3_kernel<true><<<ggrid, 256, GEMM_SMEM>>>(
        Xh, Xl, WTh + 1 * 1048576, WTl + 1 * 1048576, bk, 1.0f,
        nullptr, Kh, Kl);
    gemm_f16x3_kernel<true><<<ggrid, 256, GEMM_SMEM>>>(
        Xh, Xl, WTh + 2 * 1048576, WTl + 2 * 1048576, bv, 1.0f,
        nullptr, Vh, Vl);

    dim3 agrid(Nn / 128, Bb * 16); // (16, 64)
    attn_mma_kernel<<<agrid, 256, ATTN_SMEM>>>(Qh, Ql, Kh, Kl, Vh, Vl, pd, Oh, Ol);

    gemm_f16x3_kernel<false><<<ggrid, 256, GEMM_SMEM>>>(
        Oh, Ol, WTh + 3 * 1048576, WTl + 3 * 1048576, bo, 1.0f,
        out, nullptr, nullptr);
}

// round 12
// speedup vs baseline: 1.2206x; 1.2206x over previous
#include <cuda_runtime.h>
#include <cuda_fp16.h>
#include <cstdint>
#include <math.h>

// Shapes fixed by dataset: x:(4,2048,1024) f32, pad:(4,2048) i32,
// w*:(1024,1024) f32, b*:(1024) f32, h=16 (depth 64). out:(4,2048,1024) f32.
static const int Bb = 4;
static const int Nn = 2048;
static const int Dd = 1024;
static const int Mm = Bb * Nn; // 8192

// Scratch (no allocs allowed).
__device__ float g_Q[8192 * 1024];
__device__ float g_K[8192 * 1024];
__device__ float g_V[8192 * 1024];
__device__ float g_O[8192 * 1024];
__device__ float g_WT[4 * 1024 * 1024];

// ---------------------------------------------------------------------------
// Helpers (sm_80-era PTX: mma.sync + ldmatrix)
// ---------------------------------------------------------------------------
__device__ __forceinline__ uint32_t smem_u32(const void* p) {
    uint32_t a;
    asm("{ .reg .u64 t; cvta.to.shared.u64 t, %1; cvt.u32.u64 %0, t; }"
        : "=r"(a) : "l"(p));
    return a;
}
__device__ __forceinline__ void ldm4(uint32_t* q, uint32_t addr) {
    asm volatile("ldmatrix.sync.aligned.m8n8.x4.shared.b16 {%0,%1,%2,%3}, [%4];"
                 : "=r"(q[0]), "=r"(q[1]), "=r"(q[2]), "=r"(q[3]) : "r"(addr));
}
__device__ __forceinline__ void ldm4t(uint32_t* q, uint32_t addr) {
    asm volatile("ldmatrix.sync.aligned.m8n8.x4.trans.shared.b16 {%0,%1,%2,%3}, [%4];"
                 : "=r"(q[0]), "=r"(q[1]), "=r"(q[2]), "=r"(q[3]) : "r"(addr));
}
// fp16 mma, fp32 accumulate. NOT volatile: ptxas may reorder independent mmas.
__device__ __forceinline__ void mma_f16(float* c, const uint32_t* a,
                                        uint32_t b0, uint32_t b1) {
    asm("mma.sync.aligned.m16n8k16.row.col.f32.f16.f16.f32 "
        "{%0,%1,%2,%3}, {%4,%5,%6,%7}, {%8,%9}, {%0,%1,%2,%3};"
        : "+f"(c[0]), "+f"(c[1]), "+f"(c[2]), "+f"(c[3])
        : "r"(a[0]), "r"(a[1]), "r"(a[2]), "r"(a[3]), "r"(b0), "r"(b1));
}
__device__ __forceinline__ uint32_t pack2h(__half a, __half b) {
    __half2 t;
    t.x = a; t.y = b;
    return *reinterpret_cast<uint32_t*>(&t);
}
// Exact split: v = hi + lo (both fp16), elementwise.
__device__ __forceinline__ void split4h(float4 v, uint2& hi, uint2& lo) {
    __half hx = __float2half_rn(v.x);
    __half hy = __float2half_rn(v.y);
    __half hz = __float2half_rn(v.z);
    __half hw = __float2half_rn(v.w);
    hi = make_uint2(pack2h(hx, hy), pack2h(hz, hw));
    lo = make_uint2(
        pack2h(__float2half_rn(v.x - __half2float(hx)),
               __float2half_rn(v.y - __half2float(hy))),
        pack2h(__float2half_rn(v.z - __half2float(hz)),
               __float2half_rn(v.w - __half2float(hw))));
}

// ---------------------------------------------------------------------------
// 1024x1024 transpose: WT[n][k] = W[k][n]
// ---------------------------------------------------------------------------
__global__ __launch_bounds__(256) void transpose_k(
    const float* __restrict__ in, float* __restrict__ out)
{
    __shared__ float t[32][33];
    int x = blockIdx.x * 32 + threadIdx.x;
    int y = blockIdx.y * 32 + threadIdx.y;
#pragma unroll
    for (int j = 0; j < 32; j += 8)
        t[threadIdx.y + j][threadIdx.x] = in[(size_t)(y + j) * 1024 + x];
    __syncthreads();
    int xo = blockIdx.y * 32 + threadIdx.x;
    int yo = blockIdx.x * 32 + threadIdx.y;
#pragma unroll
    for (int j = 0; j < 32; j += 8)
        out[(size_t)(yo + j) * 1024 + xo] = t[threadIdx.x][threadIdx.y + j];
}

// ---------------------------------------------------------------------------
// fp16 3-term GEMM (R10-proven). NEW: min 2 blocks/SM for latency hiding.
// ---------------------------------------------------------------------------
static const int PANEL = 2080;               // 128*16 + 32 pad
static const int GAHI = 0;
static const int GALO = 4 * PANEL;
static const int GBHI = 8 * PANEL;
static const int GBLO = 12 * PANEL;
static const int BUFSZ = 16 * PANEL;         // 33280
static const int GEMM_SMEM = 2 * BUFSZ;      // 66560

__global__ __launch_bounds__(256, 2) void gemm_f16x3_kernel(
    const float* __restrict__ A, const float* __restrict__ BT,
    const float* __restrict__ bias, float* __restrict__ C)
{
    extern __shared__ __align__(16) char smem[];
    const uint32_t sbase = smem_u32(smem);
    const int tid = threadIdx.x;
    const int wid = tid >> 5;
    const int lane = tid & 31;
    const int wm = (wid >> 1) * 32;
    const int wn = (wid & 1) * 64;
    const int brow = blockIdx.y * 128;
    const int bcol = blockIdx.x * 128;

    const float* Ap = A + (size_t)brow * 1024;
    const float* Bp = BT + (size_t)bcol * 1024;

    float c[2][8][4];
#pragma unroll
    for (int mt = 0; mt < 2; ++mt)
#pragma unroll
        for (int nt = 0; nt < 8; ++nt)
#pragma unroll
            for (int i = 0; i < 4; ++i) c[mt][nt][i] = 0.0f;

    float4 ra[4], rb[4];
    auto load_chunk = [&](int kbase) {
#pragma unroll
        for (int i = 0; i < 4; ++i) {
            int id = tid + i * 256;
            int row = id >> 3, f4 = id & 7;
            ra[i] = *(const float4*)(Ap + (size_t)row * 1024 + kbase + f4 * 4);
            rb[i] = *(const float4*)(Bp + (size_t)row * 1024 + kbase + f4 * 4);
        }
    };
    auto store_chunk = [&](int buf) {
        char* bp = smem + buf * BUFSZ;
#pragma unroll
        for (int i = 0; i < 4; ++i) {
            int id = tid + i * 256;
            int row = id >> 3, f4 = id & 7;
            int off = (f4 >> 1) * PANEL + row * 16 + (f4 & 1) * 8;
            uint2 hi, lo;
            split4h(ra[i], hi, lo);
            *(uint2*)(bp + GAHI + off) = hi;
            *(uint2*)(bp + GALO + off) = lo;
            split4h(rb[i], hi, lo);
            *(uint2*)(bp + GBHI + off) = hi;
            *(uint2*)(bp + GBLO + off) = lo;
        }
    };

    load_chunk(0);
    store_chunk(0);
    __syncthreads();

    for (int ch = 0; ch < 32; ++ch) {
        const int buf = ch & 1;
        if (ch + 1 < 32) load_chunk((ch + 1) * 32);

        const uint32_t bb = sbase + buf * BUFSZ;
#pragma unroll
        for (int ks = 0; ks < 2; ++ks) {
            const int g0 = ks * 2;
            uint32_t Afh[2][4], Afl[2][4];       // [gg][quad]
            uint32_t Bfh[2][2][4], Bfl[2][2][4]; // [gg][ng][quad]
#pragma unroll
            for (int gg = 0; gg < 2; ++gg) {
                uint32_t arow = bb + (g0 + gg) * PANEL + (wm + lane) * 16;
                ldm4(Afh[gg], arow + GAHI);
                ldm4(Afl[gg], arow + GALO);
#pragma unroll
                for (int ng = 0; ng < 2; ++ng) {
                    uint32_t brow_ = bb + (g0 + gg) * PANEL +
                                     (wn + ng * 32 + lane) * 16;
                    ldm4(Bfh[gg][ng], brow_ + GBHI);
                    ldm4(Bfl[gg][ng], brow_ + GBLO);
                }
            }
            uint32_t ah[2][4], al[2][4];
#pragma unroll
            for (int mt = 0; mt < 2; ++mt) {
                ah[mt][0] = Afh[0][mt * 2]; ah[mt][1] = Afh[0][mt * 2 + 1];
                ah[mt][2] = Afh[1][mt * 2]; ah[mt][3] = Afh[1][mt * 2 + 1];
                al[mt][0] = Afl[0][mt * 2]; al[mt][1] = Afl[0][mt * 2 + 1];
                al[mt][2] = Afl[1][mt * 2]; al[mt][3] = Afl[1][mt * 2 + 1];
            }
            // term-major: 3 sweeps of 16 independent mmas
#pragma unroll
            for (int mt = 0; mt < 2; ++mt)
#pragma unroll
                for (int nt = 0; nt < 8; ++nt)
                    mma_f16(c[mt][nt], ah[mt],
                            Bfh[0][nt >> 2][nt & 3], Bfh[1][nt >> 2][nt & 3]);
#pragma unroll
            for (int mt = 0; mt < 2; ++mt)
#pragma unroll
                for (int nt = 0; nt < 8; ++nt)
                    mma_f16(c[mt][nt], ah[mt],
                            Bfl[0][nt >> 2][nt & 3], Bfl[1][nt >> 2][nt & 3]);
#pragma unroll
            for (int mt = 0; mt < 2; ++mt)
#pragma unroll
                for (int nt = 0; nt < 8; ++nt)
                    mma_f16(c[mt][nt], al[mt],
                            Bfh[0][nt >> 2][nt & 3], Bfh[1][nt >> 2][nt & 3]);
        }
        __syncthreads();
        if (ch + 1 < 32) {
            store_chunk(buf ^ 1);
            __syncthreads();
        }
    }

    const int r0b = brow + wm + (lane >> 2);
    const int colb = bcol + wn + 2 * (lane & 3);
#pragma unroll
    for (int mt = 0; mt < 2; ++mt) {
#pragma unroll
        for (int nt = 0; nt < 8; ++nt) {
            const int col = colb + nt * 8;
            const float2 bi = *(const float2*)(bias + col);
            const int r0 = r0b + mt * 16;
            float2 v0 = make_float2(c[mt][nt][0] + bi.x, c[mt][nt][1] + bi.y);
            float2 v1 = make_float2(c[mt][nt][2] + bi.x, c[mt][nt][3] + bi.y);
            *(float2*)(C + (size_t)r0 * 1024 + col) = v0;
            *(float2*)(C + (size_t)(r0 + 8) * 1024 + col) = v1;
        }
    }
}

// ---------------------------------------------------------------------------
// Tensor-core flash attention, fp16 3-term (R10 math), 128-KEY TILES:
// 16 mainloop iterations instead of 32 — halves online-softmax rescale
// events, shfl reductions, and loop/sync overhead. Math exactly equivalent.
// ---------------------------------------------------------------------------
static const int QPNL = 2080;                  // 128 rows * 16B + pad
static const int KPNL2 = 2080;                 // 128 key rows * 16B + pad
static const int VSTR = 144;                   // 128B row + 16 pad
static const int SQHI = 0;
static const int SQLO = 8 * QPNL;              // 16640
static const int SKHI = 16 * QPNL;             // 33280
static const int SKLO = SKHI + 8 * KPNL2;      // 49920
static const int SVHI = SKLO + 8 * KPNL2;      // 66560
static const int SVLO = SVHI + 128 * VSTR;     // 84992
static const int SAM  = SVLO + 128 * VSTR;     // 103424 (key valid flags)
static const int ATTN_SMEM = SAM + 128 * 4;    // 103936

__global__ __launch_bounds__(256) void attn_mma_kernel(
    const float* __restrict__ Q, const float* __restrict__ K,
    const float* __restrict__ V, const int* __restrict__ pad,
    float* __restrict__ O)
{
    extern __shared__ __align__(16) char smem[];
    const uint32_t sb = smem_u32(smem);
    const int tid = threadIdx.x;
    const int wid = tid >> 5;
    const int lane = tid & 31;
    const int wm = wid * 16;
    const int bh = blockIdx.y;
    const int b = bh >> 4;
    const int h = bh & 15;
    const int qbase = blockIdx.x * 128;

    // ---- stage Q tile (x 1/8) into hi/lo fp16 panels ----
#pragma unroll
    for (int i = 0; i < 8; ++i) {
        int id = tid + i * 256;
        int row = id >> 4, f4 = id & 15;
        float4 v = *(const float4*)(Q + ((size_t)(b * Nn + qbase + row)) * Dd +
                                    h * 64 + f4 * 4);
        v.x *= 0.125f; v.y *= 0.125f; v.z *= 0.125f; v.w *= 0.125f;
        uint2 hi, lo;
        split4h(v, hi, lo);
        int off = (f4 >> 1) * QPNL + row * 16 + (f4 & 1) * 8;
        *(uint2*)(smem + SQHI + off) = hi;
        *(uint2*)(smem + SQLO + off) = lo;
    }
    __syncthreads();

    uint32_t qh[4][4], ql[4][4];
#pragma unroll
    for (int kc = 0; kc < 4; ++kc) {
        uint32_t addr = sb + SQHI + (2 * kc + (lane >> 4)) * QPNL +
                        (wm + (lane & 15)) * 16;
        ldm4(qh[kc], addr);
        ldm4(ql[kc], addr + (SQLO - SQHI));
    }

    const int r = lane >> 2;
    const int qn0 = qbase + wm + r;
    const int qn1 = qn0 + 8;
    const float vn0 = (pad[b * Nn + qn0] == 0) ? 1.0f : 0.0f;
    const float vn1 = (pad[b * Nn + qn1] == 0) ? 1.0f : 0.0f;

    float o[8][4];
#pragma unroll
    for (int nd = 0; nd < 8; ++nd)
#pragma unroll
        for (int i = 0; i < 4; ++i) o[nd][i] = 0.0f;
    float m0 = -1e30f, m1 = -1e30f, l0 = 0.0f, l1 = 0.0f;

    for (int kt = 0; kt < Nn; kt += 128) {
        __syncthreads();
        // ---- stage 128 keys: K hi/lo panels + V hi/lo rows ----
#pragma unroll
        for (int i = 0; i < 16; ++i) {
            int id = tid + i * 256;       // 0..4095
            int part = id >> 11;          // 0 = K, 1 = V
            int idx = id & 2047;
            int row = idx >> 4;           // 0..127
            int f4 = idx & 15;
            size_t g = ((size_t)(b * Nn + kt + row)) * Dd + h * 64 + f4 * 4;
            uint2 hi, lo;
            if (part == 0) {
                split4h(*(const float4*)(K + g), hi, lo);
                int koff = (f4 >> 1) * KPNL2 + row * 16 + (f4 & 1) * 8;
                *(uint2*)(smem + SKHI + koff) = hi;
                *(uint2*)(smem + SKLO + koff) = lo;
            } else {
                split4h(*(const float4*)(V + g), hi, lo);
                int voff = row * VSTR + f4 * 8;
                *(uint2*)(smem + SVHI + voff) = hi;
                *(uint2*)(smem + SVLO + voff) = lo;
            }
        }
        if (tid < 128)
            *(float*)(smem + SAM + tid * 4) =
                (pad[b * Nn + kt + tid] == 0) ? 1.0f : 0.0f;
        __syncthreads();

        // ---- S = qh Kh + qh Kl + ql Kh over 128 keys ----
        float s[16][4];
#pragma unroll
        for (int nt = 0; nt < 16; ++nt)
#pragma unroll
            for (int i = 0; i < 4; ++i) s[nt][i] = 0.0f;

#pragma unroll
        for (int kc = 0; kc < 4; ++kc) {
#pragma unroll
            for (int half = 0; half < 2; ++half) {
                uint32_t b0h[4], b4h[4], b1h[4], b5h[4];
                uint32_t b0l[4], b4l[4], b1l[4], b5l[4];
                uint32_t p0 = sb + SKHI + (2 * kc) * KPNL2 +
                              half * 64 * 16 + lane * 16;
                uint32_t p1 = p0 + KPNL2;
                ldm4(b0h, p0);
                ldm4(b4h, p0 + 32 * 16);
                ldm4(b1h, p1);
                ldm4(b5h, p1 + 32 * 16);
                ldm4(b0l, p0 + (SKLO - SKHI));
                ldm4(b4l, p0 + 32 * 16 + (SKLO - SKHI));
                ldm4(b1l, p1 + (SKLO - SKHI));
                ldm4(b5l, p1 + 32 * 16 + (SKLO - SKHI));
                float* sh = (float*)s[half * 8];
#pragma unroll
                for (int nt = 0; nt < 8; ++nt)
                    mma_f16(sh + nt * 4, qh[kc],
                            (nt < 4) ? b0h[nt] : b4h[nt - 4],
                            (nt < 4) ? b1h[nt] : b5h[nt - 4]);
#pragma unroll
                for (int nt = 0; nt < 8; ++nt)
                    mma_f16(sh + nt * 4, qh[kc],
                            (nt < 4) ? b0l[nt] : b4l[nt - 4],
                            (nt < 4) ? b1l[nt] : b5l[nt - 4]);
#pragma unroll
                for (int nt = 0; nt < 8; ++nt)
                    mma_f16(sh + nt * 4, ql[kc],
                            (nt < 4) ? b0h[nt] : b4h[nt - 4],
                            (nt < 4) ? b1h[nt] : b5h[nt - 4]);
            }
        }

        // ---- mask (exact-zero form) + ONE online-softmax update / 128 keys
        float tm0 = -1e30f, tm1 = -1e30f;
#pragma unroll
        for (int nt = 0; nt < 16; ++nt) {
            float2 vm = *(const float2*)(smem + SAM +
                                         (nt * 8 + 2 * (lane & 3)) * 4);
            s[nt][0] = fmaf(1.0f - vn0 * vm.x, -1e6f, s[nt][0]);
            s[nt][1] = fmaf(1.0f - vn0 * vm.y, -1e6f, s[nt][1]);
            s[nt][2] = fmaf(1.0f - vn1 * vm.x, -1e6f, s[nt][2]);
            s[nt][3] = fmaf(1.0f - vn1 * vm.y, -1e6f, s[nt][3]);
            tm0 = fmaxf(tm0, fmaxf(s[nt][0], s[nt][1]));
            tm1 = fmaxf(tm1, fmaxf(s[nt][2], s[nt][3]));
        }
        tm0 = fmaxf(tm0, __shfl_xor_sync(0xffffffffu, tm0, 1));
        tm0 = fmaxf(tm0, __shfl_xor_sync(0xffffffffu, tm0, 2));
        tm1 = fmaxf(tm1, __shfl_xor_sync(0xffffffffu, tm1, 1));
        tm1 = fmaxf(tm1, __shfl_xor_sync(0xffffffffu, tm1, 2));

        float m0n = fmaxf(m0, tm0), m1n = fmaxf(m1, tm1);
        float a0 = __expf(m0 - m0n), a1 = __expf(m1 - m1n);
        m0 = m0n; m1 = m1n;

        float sum0 = 0.0f, sum1 = 0.0f;
#pragma unroll
        for (int nt = 0; nt < 16; ++nt) {
            s[nt][0] = __expf(s[nt][0] - m0);
            s[nt][1] = __expf(s[nt][1] - m0);
            s[nt][2] = __expf(s[nt][2] - m1);
            s[nt][3] = __expf(s[nt][3] - m1);
            sum0 += s[nt][0] + s[nt][1];
            sum1 += s[nt][2] + s[nt][3];
        }
        sum0 += __shfl_xor_sync(0xffffffffu, sum0, 1);
        sum0 += __shfl_xor_sync(0xffffffffu, sum0, 2);
        sum1 += __shfl_xor_sync(0xffffffffu, sum1, 1);
        sum1 += __shfl_xor_sync(0xffffffffu, sum1, 2);
        l0 = l0 * a0 + sum0;
        l1 = l1 * a1 + sum1;
#pragma unroll
        for (int nd = 0; nd < 8; ++nd) {
            o[nd][0] *= a0; o[nd][1] *= a0;
            o[nd][2] *= a1; o[nd][3] *= a1;
        }

        // ---- O += Ph Vh + Ph Vl + Pl Vh over 128 keys ----
#pragma unroll
        for (int kc = 0; kc < 8; ++kc) {
            uint32_t ph[4], pl[4];
            {
                const float* pa = s[2 * kc];
                const float* pb = s[2 * kc + 1];
                __half h0 = __float2half_rn(pa[0]);
                __half h1 = __float2half_rn(pa[1]);
                __half h2 = __float2half_rn(pa[2]);
                __half h3 = __float2half_rn(pa[3]);
                __half h4 = __float2half_rn(pb[0]);
                __half h5 = __float2half_rn(pb[1]);
                __half h6 = __float2half_rn(pb[2]);
                __half h7 = __float2half_rn(pb[3]);
                ph[0] = pack2h(h0, h1);
                ph[1] = pack2h(h2, h3);
                ph[2] = pack2h(h4, h5);
                ph[3] = pack2h(h6, h7);
                pl[0] = pack2h(__float2half_rn(pa[0] - __half2float(h0)),
                               __float2half_rn(pa[1] - __half2float(h1)));
                pl[1] = pack2h(__float2half_rn(pa[2] - __half2float(h2)),
                               __float2half_rn(pa[3] - __half2float(h3)));
                pl[2] = pack2h(__float2half_rn(pb[0] - __half2float(h4)),
                               __float2half_rn(pb[1] - __half2float(h5)));
                pl[3] = pack2h(__float2half_rn(pb[2] - __half2float(h6)),
                               __float2half_rn(pb[3] - __half2float(h7)));
            }
            uint32_t vh[4][4], vl[4][4];
#pragma unroll
            for (int jj = 0; jj < 4; ++jj) {
                uint32_t va = sb + SVHI + (kc * 16 + (lane & 15)) * VSTR +
                              (2 * jj + (lane >> 4)) * 16;
                ldm4t(vh[jj], va);
                ldm4t(vl[jj], va + (SVLO - SVHI));
            }
#pragma unroll
            for (int jj = 0; jj < 4; ++jj) {
                mma_f16(o[2 * jj], ph, vh[jj][0], vh[jj][1]);
                mma_f16(o[2 * jj + 1], ph, vh[jj][2], vh[jj][3]);
            }
#pragma unroll
            for (int jj = 0; jj < 4; ++jj) {
                mma_f16(o[2 * jj], ph, vl[jj][0], vl[jj][1]);
                mma_f16(o[2 * jj + 1], ph, vl[jj][2], vl[jj][3]);
            }
#pragma unroll
            for (int jj = 0; jj < 4; ++jj) {
                mma_f16(o[2 * jj], pl, vh[jj][0], vh[jj][1]);
                mma_f16(o[2 * jj + 1], pl, vh[jj][2], vh[jj][3]);
            }
        }
    }

    // ---- epilogue ----
    const float inv0 = 1.0f / l0, inv1 = 1.0f / l1;
    const size_t row0 = (size_t)(b * Nn + qn0) * Dd;
    const size_t row1 = (size_t)(b * Nn + qn1) * Dd;
#pragma unroll
    for (int nd = 0; nd < 8; ++nd) {
        const int col = h * 64 + nd * 8 + 2 * (lane & 3);
        *(float2*)(O + row0 + col) =
            make_float2(o[nd][0] * inv0, o[nd][1] * inv0);
        *(float2*)(O + row1 + col) =
            make_float2(o[nd][2] * inv1, o[nd][3] * inv1);
    }
}

// ---------------------------------------------------------------------------
// Launch
// ---------------------------------------------------------------------------
extern "C" void kernel_launch(void* const* d_in, const int* in_sizes, int n_in,
                              void* d_out, int out_size)
{
    const float* x  = (const float*)d_in[0];
    const int*   pd = (const int*)d_in[1];
    const float* wq = (const float*)d_in[2];
    const float* bq = (const float*)d_in[3];
    const float* wk = (const float*)d_in[4];
    const float* bk = (const float*)d_in[5];
    const float* wv = (const float*)d_in[6];
    const float* bv = (const float*)d_in[7];
    const float* wo = (const float*)d_in[8];
    const float* bo = (const float*)d_in[9];
    float* out = (float*)d_out;

    float *Q, *K, *V, *O, *WT;
    cudaGetSymbolAddress((void**)&Q, g_Q);
    cudaGetSymbolAddress((void**)&K, g_K);
    cudaGetSymbolAddress((void**)&V, g_V);
    cudaGetSymbolAddress((void**)&O, g_O);
    cudaGetSymbolAddress((void**)&WT, g_WT);

    cudaFuncSetAttribute(gemm_f16x3_kernel,
                         cudaFuncAttributeMaxDynamicSharedMemorySize, GEMM_SMEM);
    cudaFuncSetAttribute(attn_mma_kernel,
                         cudaFuncAttributeMaxDynamicSharedMemorySize, ATTN_SMEM);

    dim3 tgrid(32, 32), tblk(32, 8);
    transpose_k<<<tgrid, tblk>>>(wq, WT + 0 * 1024 * 1024);
    transpose_k<<<tgrid, tblk>>>(wk, WT + 1 * 1024 * 1024);
    transpose_k<<<tgrid, tblk>>>(wv, WT + 2 * 1024 * 1024);
    transpose_k<<<tgrid, tblk>>>(wo, WT + 3 * 1024 * 1024);

    dim3 ggrid(Dd / 128, Mm / 128); // (8, 64)
    gemm_f16x3_kernel<<<ggrid, 256, GEMM_SMEM>>>(x, WT + 0 * 1024 * 1024, bq, Q);
    gemm_f16x3_kernel<<<ggrid, 256, GEMM_SMEM>>>(x, WT + 1 * 1024 * 1024, bk, K);
    gemm_f16x3_kernel<<<ggrid, 256, GEMM_SMEM>>>(x, WT + 2 * 1024 * 1024, bv, V);

    dim3 agrid(Nn / 128, Bb * 16); // (16, 64)
    attn_mma_kernel<<<agrid, 256, ATTN_SMEM>>>(Q, K, V, pd, O);

    gemm_f16x3_kernel<<<ggrid, 256, GEMM_SMEM>>>(O, WT + 3 * 1024 * 1024, bo, out);
}

// round 14
// speedup vs baseline: 1.3284x; 1.0883x over previous
// R14 = R13 resubmitted unchanged (R13 bench aborted on a container-level
// failure with no compile/run output; sync-structure audit found no race or
// deadlock; treating as infra flake and re-running the same experiment).
#include <cuda_runtime.h>
#include <cuda_fp16.h>
#include <cstdint>
#include <math.h>

// Shapes fixed by dataset: x:(4,2048,1024) f32, pad:(4,2048) i32,
// w*:(1024,1024) f32, b*:(1024) f32, h=16 (depth 64). out:(4,2048,1024) f32.
static const int Bb = 4;
static const int Nn = 2048;
static const int Dd = 1024;
static const int Mm = Bb * Nn; // 8192

// Scratch (no allocs allowed).
__device__ float g_Q[8192 * 1024];
__device__ float g_K[8192 * 1024];
__device__ float g_V[8192 * 1024];
__device__ float g_O[8192 * 1024];
__device__ float g_WT[4 * 1024 * 1024];

// ---------------------------------------------------------------------------
// Helpers (sm_80-era PTX: mma.sync + ldmatrix)
// ---------------------------------------------------------------------------
__device__ __forceinline__ uint32_t smem_u32(const void* p) {
    uint32_t a;
    asm("{ .reg .u64 t; cvta.to.shared.u64 t, %1; cvt.u32.u64 %0, t; }"
        : "=r"(a) : "l"(p));
    return a;
}
__device__ __forceinline__ void ldm4(uint32_t* q, uint32_t addr) {
    asm volatile("ldmatrix.sync.aligned.m8n8.x4.shared.b16 {%0,%1,%2,%3}, [%4];"
                 : "=r"(q[0]), "=r"(q[1]), "=r"(q[2]), "=r"(q[3]) : "r"(addr));
}
__device__ __forceinline__ void ldm4t(uint32_t* q, uint32_t addr) {
    asm volatile("ldmatrix.sync.aligned.m8n8.x4.trans.shared.b16 {%0,%1,%2,%3}, [%4];"
                 : "=r"(q[0]), "=r"(q[1]), "=r"(q[2]), "=r"(q[3]) : "r"(addr));
}
// fp16 mma, fp32 accumulate. NOT volatile: ptxas may reorder independent mmas.
__device__ __forceinline__ void mma_f16(float* c, const uint32_t* a,
                                        uint32_t b0, uint32_t b1) {
    asm("mma.sync.aligned.m16n8k16.row.col.f32.f16.f16.f32 "
        "{%0,%1,%2,%3}, {%4,%5,%6,%7}, {%8,%9}, {%0,%1,%2,%3};"
        : "+f"(c[0]), "+f"(c[1]), "+f"(c[2]), "+f"(c[3])
        : "r"(a[0]), "r"(a[1]), "r"(a[2]), "r"(a[3]), "r"(b0), "r"(b1));
}
__device__ __forceinline__ uint32_t pack2h(__half a, __half b) {
    __half2 t;
    t.x = a; t.y = b;
    return *reinterpret_cast<uint32_t*>(&t);
}
// Exact split: v = hi + lo (both fp16), elementwise.
__device__ __forceinline__ void split4h(float4 v, uint2& hi, uint2& lo) {
    __half hx = __float2half_rn(v.x);
    __half hy = __float2half_rn(v.y);
    __half hz = __float2half_rn(v.z);
    __half hw = __float2half_rn(v.w);
    hi = make_uint2(pack2h(hx, hy), pack2h(hz, hw));
    lo = make_uint2(
        pack2h(__float2half_rn(v.x - __half2float(hx)),
               __float2half_rn(v.y - __half2float(hy))),
        pack2h(__float2half_rn(v.z - __half2float(hz)),
               __float2half_rn(v.w - __half2float(hw))));
}

// ---------------------------------------------------------------------------
// 1024x1024 transpose: WT[n][k] = W[k][n]
// ---------------------------------------------------------------------------
__global__ __launch_bounds__(256) void transpose_k(
    const float* __restrict__ in, float* __restrict__ out)
{
    __shared__ float t[32][33];
    int x = blockIdx.x * 32 + threadIdx.x;
    int y = blockIdx.y * 32 + threadIdx.y;
#pragma unroll
    for (int j = 0; j < 32; j += 8)
        t[threadIdx.y + j][threadIdx.x] = in[(size_t)(y + j) * 1024 + x];
    __syncthreads();
    int xo = blockIdx.y * 32 + threadIdx.x;
    int yo = blockIdx.x * 32 + threadIdx.y;
#pragma unroll
    for (int j = 0; j < 32; j += 8)
        out[(size_t)(yo + j) * 1024 + xo] = t[threadIdx.x][threadIdx.y + j];
}

// ---------------------------------------------------------------------------
// fp16 3-term GEMM (R10 math). ONE sync per chunk (store targets the buffer
// nobody reads this iteration; prior sync protects it from stale readers).
// ---------------------------------------------------------------------------
static const int PANEL = 2080;               // 128*16 + 32 pad
static const int GAHI = 0;
static const int GALO = 4 * PANEL;
static const int GBHI = 8 * PANEL;
static const int GBLO = 12 * PANEL;
static const int BUFSZ = 16 * PANEL;         // 33280
static const int GEMM_SMEM = 2 * BUFSZ;      // 66560

__global__ __launch_bounds__(256) void gemm_f16x3_kernel(
    const float* __restrict__ A, const float* __restrict__ BT,
    const float* __restrict__ bias, float* __restrict__ C)
{
    extern __shared__ __align__(16) char smem[];
    const uint32_t sbase = smem_u32(smem);
    const int tid = threadIdx.x;
    const int wid = tid >> 5;
    const int lane = tid & 31;
    const int wm = (wid >> 1) * 32;
    const int wn = (wid & 1) * 64;
    const int brow = blockIdx.y * 128;
    const int bcol = blockIdx.x * 128;

    const float* Ap = A + (size_t)brow * 1024;
    const float* Bp = BT + (size_t)bcol * 1024;

    float c[2][8][4];
#pragma unroll
    for (int mt = 0; mt < 2; ++mt)
#pragma unroll
        for (int nt = 0; nt < 8; ++nt)
#pragma unroll
            for (int i = 0; i < 4; ++i) c[mt][nt][i] = 0.0f;

    float4 ra[4], rb[4];
    auto load_chunk = [&](int kbase) {
#pragma unroll
        for (int i = 0; i < 4; ++i) {
            int id = tid + i * 256;
            int row = id >> 3, f4 = id & 7;
            ra[i] = *(const float4*)(Ap + (size_t)row * 1024 + kbase + f4 * 4);
            rb[i] = *(const float4*)(Bp + (size_t)row * 1024 + kbase + f4 * 4);
        }
    };
    auto store_chunk = [&](int buf) {
        char* bp = smem + buf * BUFSZ;
#pragma unroll
        for (int i = 0; i < 4; ++i) {
            int id = tid + i * 256;
            int row = id >> 3, f4 = id & 7;
            int off = (f4 >> 1) * PANEL + row * 16 + (f4 & 1) * 8;
            uint2 hi, lo;
            split4h(ra[i], hi, lo);
            *(uint2*)(bp + GAHI + off) = hi;
            *(uint2*)(bp + GALO + off) = lo;
            split4h(rb[i], hi, lo);
            *(uint2*)(bp + GBHI + off) = hi;
            *(uint2*)(bp + GBLO + off) = lo;
        }
    };

    load_chunk(0);
    store_chunk(0);
    __syncthreads();

    for (int ch = 0; ch < 32; ++ch) {
        const int buf = ch & 1;
        if (ch + 1 < 32) load_chunk((ch + 1) * 32);

        const uint32_t bb = sbase + buf * BUFSZ;
#pragma unroll
        for (int ks = 0; ks < 2; ++ks) {
            const int g0 = ks * 2;
            uint32_t Afh[2][4], Afl[2][4];       // [gg][quad]
            uint32_t Bfh[2][2][4], Bfl[2][2][4]; // [gg][ng][quad]
#pragma unroll
            for (int gg = 0; gg < 2; ++gg) {
                uint32_t arow = bb + (g0 + gg) * PANEL + (wm + lane) * 16;
                ldm4(Afh[gg], arow + GAHI);
                ldm4(Afl[gg], arow + GALO);
#pragma unroll
                for (int ng = 0; ng < 2; ++ng) {
                    uint32_t brow_ = bb + (g0 + gg) * PANEL +
                                     (wn + ng * 32 + lane) * 16;
                    ldm4(Bfh[gg][ng], brow_ + GBHI);
                    ldm4(Bfl[gg][ng], brow_ + GBLO);
                }
            }
            uint32_t ah[2][4], al[2][4];
#pragma unroll
            for (int mt = 0; mt < 2; ++mt) {
                ah[mt][0] = Afh[0][mt * 2]; ah[mt][1] = Afh[0][mt * 2 + 1];
                ah[mt][2] = Afh[1][mt * 2]; ah[mt][3] = Afh[1][mt * 2 + 1];
                al[mt][0] = Afl[0][mt * 2]; al[mt][1] = Afl[0][mt * 2 + 1];
                al[mt][2] = Afl[1][mt * 2]; al[mt][3] = Afl[1][mt * 2 + 1];
            }
            // term-major: 3 sweeps of 16 independent mmas
#pragma unroll
            for (int mt = 0; mt < 2; ++mt)
#pragma unroll
                for (int nt = 0; nt < 8; ++nt)
                    mma_f16(c[mt][nt], ah[mt],
                            Bfh[0][nt >> 2][nt & 3], Bfh[1][nt >> 2][nt & 3]);
#pragma unroll
            for (int mt = 0; mt < 2; ++mt)
#pragma unroll
                for (int nt = 0; nt < 8; ++nt)
                    mma_f16(c[mt][nt], ah[mt],
                            Bfl[0][nt >> 2][nt & 3], Bfl[1][nt >> 2][nt & 3]);
#pragma unroll
            for (int mt = 0; mt < 2; ++mt)
#pragma unroll
                for (int nt = 0; nt < 8; ++nt)
                    mma_f16(c[mt][nt], al[mt],
                            Bfh[0][nt >> 2][nt & 3], Bfh[1][nt >> 2][nt & 3]);
        }
        if (ch + 1 < 32) store_chunk(buf ^ 1);
        __syncthreads();
    }

    const int r0b = brow + wm + (lane >> 2);
    const int colb = bcol + wn + 2 * (lane & 3);
#pragma unroll
    for (int mt = 0; mt < 2; ++mt) {
#pragma unroll
        for (int nt = 0; nt < 8; ++nt) {
            const int col = colb + nt * 8;
            const float2 bi = *(const float2*)(bias + col);
            const int r0 = r0b + mt * 16;
            float2 v0 = make_float2(c[mt][nt][0] + bi.x, c[mt][nt][1] + bi.y);
            float2 v1 = make_float2(c[mt][nt][2] + bi.x, c[mt][nt][3] + bi.y);
            *(float2*)(C + (size_t)r0 * 1024 + col) = v0;
            *(float2*)(C + (size_t)(r0 + 8) * 1024 + col) = v1;
        }
    }
}

// ---------------------------------------------------------------------------
// Tensor-core flash attention, fp16 3-term (R10 math, 64-key tiles).
// Double-buffered K/V smem + register prefetch of the next tile's global
// loads -> ONE sync per tile; gmem latency hidden under mma work.
// ---------------------------------------------------------------------------
static const int QPNL = 2080;                 // 128 rows * 16B + pad
static const int KPNL = 1056;                 // 64 rows * 16B + pad
static const int VSTR = 144;                  // 128B row + 16 pad
static const int SQHI = 0;
static const int SQLO = 8 * QPNL;             // 16640
static const int SBUF0 = 16 * QPNL;           // 33280
// per-buffer layout
static const int AKHI = 0;
static const int AKLO = 8 * KPNL;             // 8448
static const int AVHI = 16 * KPNL;            // 16896
static const int AVLO = AVHI + 64 * VSTR;     // 26112
static const int AMSK = AVLO + 64 * VSTR;     // 35328
static const int BUFSTR = AMSK + 64 * 4;      // 35584
static const int ATTN_SMEM = SBUF0 + 2 * BUFSTR; // 104448

__global__ __launch_bounds__(256) void attn_mma_kernel(
    const float* __restrict__ Q, const float* __restrict__ K,
    const float* __restrict__ V, const int* __restrict__ pad,
    float* __restrict__ O)
{
    extern __shared__ __align__(16) char smem[];
    const uint32_t sb = smem_u32(smem);
    const int tid = threadIdx.x;
    const int wid = tid >> 5;
    const int lane = tid & 31;
    const int wm = wid * 16;
    const int bh = blockIdx.y;
    const int b = bh >> 4;
    const int h = bh & 15;
    const int qbase = blockIdx.x * 128;

    // ---- stage Q tile (x 1/8) into hi/lo fp16 panels ----
#pragma unroll
    for (int i = 0; i < 8; ++i) {
        int id = tid + i * 256;
        int row = id >> 4, f4 = id & 15;
        float4 v = *(const float4*)(Q + ((size_t)(b * Nn + qbase + row)) * Dd +
                                    h * 64 + f4 * 4);
        v.x *= 0.125f; v.y *= 0.125f; v.z *= 0.125f; v.w *= 0.125f;
        uint2 hi, lo;
        split4h(v, hi, lo);
        int off = (f4 >> 1) * QPNL + row * 16 + (f4 & 1) * 8;
        *(uint2*)(smem + SQHI + off) = hi;
        *(uint2*)(smem + SQLO + off) = lo;
    }

    // ---- K/V register prefetch + split/store machinery ----
    float4 rk[4], rv[4];
    auto load_kv = [&](int kt) {
#pragma unroll
        for (int i = 0; i < 4; ++i) {
            int id = tid + i * 256;
            int row = id >> 4, f4 = id & 15;
            size_t g = ((size_t)(b * Nn + kt + row)) * Dd + h * 64 + f4 * 4;
            rk[i] = *(const float4*)(K + g);
            rv[i] = *(const float4*)(V + g);
        }
    };
    auto store_kv = [&](int buf) {
        char* bp = smem + SBUF0 + buf * BUFSTR;
#pragma unroll
        for (int i = 0; i < 4; ++i) {
            int id = tid + i * 256;
            int row = id >> 4, f4 = id & 15;
            uint2 hi, lo;
            split4h(rk[i], hi, lo);
            int koff = (f4 >> 1) * KPNL + row * 16 + (f4 & 1) * 8;
            *(uint2*)(bp + AKHI + koff) = hi;
            *(uint2*)(bp + AKLO + koff) = lo;
            split4h(rv[i], hi, lo);
            int voff = row * VSTR + f4 * 8;
            *(uint2*)(bp + AVHI + voff) = hi;
            *(uint2*)(bp + AVLO + voff) = lo;
        }
    };
    auto store_mask = [&](int buf, int kt) {
        if (tid < 64)
            *(float*)(smem + SBUF0 + buf * BUFSTR + AMSK + tid * 4) =
                (pad[b * Nn + kt + tid] == 0) ? 1.0f : 0.0f;
    };

    load_kv(0);
    store_kv(0);
    store_mask(0, 0);
    __syncthreads();

    // ---- Q fragments to registers ----
    uint32_t qh[4][4], ql[4][4];
#pragma unroll
    for (int kc = 0; kc < 4; ++kc) {
        uint32_t addr = sb + SQHI + (2 * kc + (lane >> 4)) * QPNL +
                        (wm + (lane & 15)) * 16;
        ldm4(qh[kc], addr);
        ldm4(ql[kc], addr + (SQLO - SQHI));
    }

    const int r = lane >> 2;
    const int qn0 = qbase + wm + r;
    const int qn1 = qn0 + 8;
    const float vn0 = (pad[b * Nn + qn0] == 0) ? 1.0f : 0.0f;
    const float vn1 = (pad[b * Nn + qn1] == 0) ? 1.0f : 0.0f;

    float o[8][4];
#pragma unroll
    for (int nd = 0; nd < 8; ++nd)
#pragma unroll
        for (int i = 0; i < 4; ++i) o[nd][i] = 0.0f;
    float m0 = -1e30f, m1 = -1e30f, l0 = 0.0f, l1 = 0.0f;

    for (int t = 0; t < 32; ++t) {
        const int buf = t & 1;
        if (t + 1 < 32) load_kv((t + 1) * 64);   // prefetch: overlapped w/ mma

        const uint32_t kb = sb + SBUF0 + buf * BUFSTR;
        const char* mp = smem + SBUF0 + buf * BUFSTR + AMSK;

        // ---- S = qh Kh + qh Kl + ql Kh ----
        float s[8][4];
#pragma unroll
        for (int nt = 0; nt < 8; ++nt)
#pragma unroll
            for (int i = 0; i < 4; ++i) s[nt][i] = 0.0f;

#pragma unroll
        for (int kc = 0; kc < 4; ++kc) {
            uint32_t b0h[4], b4h[4], b1h[4], b5h[4];
            uint32_t b0l[4], b4l[4], b1l[4], b5l[4];
            uint32_t p0 = kb + AKHI + (2 * kc) * KPNL + lane * 16;
            uint32_t p1 = p0 + KPNL;
            ldm4(b0h, p0);
            ldm4(b4h, p0 + 32 * 16);
            ldm4(b1h, p1);
            ldm4(b5h, p1 + 32 * 16);
            ldm4(b0l, p0 + (AKLO - AKHI));
            ldm4(b4l, p0 + 32 * 16 + (AKLO - AKHI));
            ldm4(b1l, p1 + (AKLO - AKHI));
            ldm4(b5l, p1 + 32 * 16 + (AKLO - AKHI));
#pragma unroll
            for (int nt = 0; nt < 8; ++nt)
                mma_f16(s[nt], qh[kc],
                        (nt < 4) ? b0h[nt] : b4h[nt - 4],
                        (nt < 4) ? b1h[nt] : b5h[nt - 4]);
#pragma unroll
            for (int nt = 0; nt < 8; ++nt)
                mma_f16(s[nt], qh[kc],
                        (nt < 4) ? b0l[nt] : b4l[nt - 4],
                        (nt < 4) ? b1l[nt] : b5l[nt - 4]);
#pragma unroll
            for (int nt = 0; nt < 8; ++nt)
                mma_f16(s[nt], ql[kc],
                        (nt < 4) ? b0h[nt] : b4h[nt - 4],
                        (nt < 4) ? b1h[nt] : b5h[nt - 4]);
        }

        // ---- mask (exact-zero form) + online softmax ----
        float tm0 = -1e30f, tm1 = -1e30f;
#pragma unroll
        for (int nt = 0; nt < 8; ++nt) {
            float2 vm = *(const float2*)(mp + (nt * 8 + 2 * (lane & 3)) * 4);
            s[nt][0] = fmaf(1.0f - vn0 * vm.x, -1e6f, s[nt][0]);
            s[nt][1] = fmaf(1.0f - vn0 * vm.y, -1e6f, s[nt][1]);
            s[nt][2] = fmaf(1.0f - vn1 * vm.x, -1e6f, s[nt][2]);
            s[nt][3] = fmaf(1.0f - vn1 * vm.y, -1e6f, s[nt][3]);
            tm0 = fmaxf(tm0, fmaxf(s[nt][0], s[nt][1]));
            tm1 = fmaxf(tm1, fmaxf(s[nt][2], s[nt][3]));
        }
        tm0 = fmaxf(tm0, __shfl_xor_sync(0xffffffffu, tm0, 1));
        tm0 = fmaxf(tm0, __shfl_xor_sync(0xffffffffu, tm0, 2));
        tm1 = fmaxf(tm1, __shfl_xor_sync(0xffffffffu, tm1, 1));
        tm1 = fmaxf(tm1, __shfl_xor_sync(0xffffffffu, tm1, 2));

        float m0n = fmaxf(m0, tm0), m1n = fmaxf(m1, tm1);
        float a0 = __expf(m0 - m0n), a1 = __expf(m1 - m1n);
        m0 = m0n; m1 = m1n;

        float sum0 = 0.0f, sum1 = 0.0f;
#pragma unroll
        for (int nt = 0; nt < 8; ++nt) {
            s[nt][0] = __expf(s[nt][0] - m0);
            s[nt][1] = __expf(s[nt][1] - m0);
            s[nt][2] = __expf(s[nt][2] - m1);
            s[nt][3] = __expf(s[nt][3] - m1);
            sum0 += s[nt][0] + s[nt][1];
            sum1 += s[nt][2] + s[nt][3];
        }
        sum0 += __shfl_xor_sync(0xffffffffu, sum0, 1);
        sum0 += __shfl_xor_sync(0xffffffffu, sum0, 2);
        sum1 += __shfl_xor_sync(0xffffffffu, sum1, 1);
        sum1 += __shfl_xor_sync(0xffffffffu, sum1, 2);
        l0 = l0 * a0 + sum0;
        l1 = l1 * a1 + sum1;
#pragma unroll
        for (int nd = 0; nd < 8; ++nd) {
            o[nd][0] *= a0; o[nd][1] *= a0;
            o[nd][2] *= a1; o[nd][3] *= a1;
        }

        // ---- O += Ph Vh + Ph Vl + Pl Vh ----
#pragma unroll
        for (int kc = 0; kc < 4; ++kc) {
            uint32_t ph[4], pl[4];
            {
                const float* pa = s[2 * kc];
                const float* pb = s[2 * kc + 1];
                __half h0 = __float2half_rn(pa[0]);
                __half h1 = __float2half_rn(pa[1]);
                __half h2 = __float2half_rn(pa[2]);
                __half h3 = __float2half_rn(pa[3]);
                __half h4 = __float2half_rn(pb[0]);
                __half h5 = __float2half_rn(pb[1]);
                __half h6 = __float2half_rn(pb[2]);
                __half h7 = __float2half_rn(pb[3]);
                ph[0] = pack2h(h0, h1);
                ph[1] = pack2h(h2, h3);
                ph[2] = pack2h(h4, h5);
                ph[3] = pack2h(h6, h7);
                pl[0] = pack2h(__float2half_rn(pa[0] - __half2float(h0)),
                               __float2half_rn(pa[1] - __half2float(h1)));
                pl[1] = pack2h(__float2half_rn(pa[2] - __half2float(h2)),
                               __float2half_rn(pa[3] - __half2float(h3)));
                pl[2] = pack2h(__float2half_rn(pb[0] - __half2float(h4)),
                               __float2half_rn(pb[1] - __half2float(h5)));
                pl[3] = pack2h(__float2half_rn(pb[2] - __half2float(h6)),
                               __float2half_rn(pb[3] - __half2float(h7)));
            }
            uint32_t vh[4][4], vl[4][4];
#pragma unroll
            for (int jj = 0; jj < 4; ++jj) {
                uint32_t va = kb + AVHI + (kc * 16 + (lane & 15)) * VSTR +
                              (2 * jj + (lane >> 4)) * 16;
                ldm4t(vh[jj], va);
                ldm4t(vl[jj], va + (AVLO - AVHI));
            }
#pragma unroll
            for (int jj = 0; jj < 4; ++jj) {
                mma_f16(o[2 * jj], ph, vh[jj][0], vh[jj][1]);
                mma_f16(o[2 * jj + 1], ph, vh[jj][2], vh[jj][3]);
            }
#pragma unroll
            for (int jj = 0; jj < 4; ++jj) {
                mma_f16(o[2 * jj], ph, vl[jj][0], vl[jj][1]);
                mma_f16(o[2 * jj + 1], ph, vl[jj][2], vl[jj][3]);
            }
#pragma unroll
            for (int jj = 0; jj < 4; ++jj) {
                mma_f16(o[2 * jj], pl, vh[jj][0], vh[jj][1]);
                mma_f16(o[2 * jj + 1], pl, vh[jj][2], vh[jj][3]);
            }
        }

        if (t + 1 < 32) {
            store_kv(buf ^ 1);
            store_mask(buf ^ 1, (t + 1) * 64);
        }
        __syncthreads();
    }

    // ---- epilogue ----
    const float inv0 = 1.0f / l0, inv1 = 1.0f / l1;
    const size_t row0 = (size_t)(b * Nn + qn0) * Dd;
    const size_t row1 = (size_t)(b * Nn + qn1) * Dd;
#pragma unroll
    for (int nd = 0; nd < 8; ++nd) {
        const int col = h * 64 + nd * 8 + 2 * (lane & 3);
        *(float2*)(O + row0 + col) =
            make_float2(o[nd][0] * inv0, o[nd][1] * inv0);
        *(float2*)(O + row1 + col) =
            make_float2(o[nd][2] * inv1, o[nd][3] * inv1);
    }
}

// ---------------------------------------------------------------------------
// Launch
// ---------------------------------------------------------------------------
extern "C" void kernel_launch(void* const* d_in, const int* in_sizes, int n_in,
                              void* d_out, int out_size)
{
    const float* x  = (const float*)d_in[0];
    const int*   pd = (const int*)d_in[1];
    const float* wq = (const float*)d_in[2];
    const float* bq = (const float*)d_in[3];
    const float* wk = (const float*)d_in[4];
    const float* bk = (const float*)d_in[5];
    const float* wv = (const float*)d_in[6];
    const float* bv = (const float*)d_in[7];
    const float* wo = (const float*)d_in[8];
    const float* bo = (const float*)d_in[9];
    float* out = (float*)d_out;

    float *Q, *K, *V, *O, *WT;
    cudaGetSymbolAddress((void**)&Q, g_Q);
    cudaGetSymbolAddress((void**)&K, g_K);
    cudaGetSymbolAddress((void**)&V, g_V);
    cudaGetSymbolAddress((void**)&O, g_O);
    cudaGetSymbolAddress((void**)&WT, g_WT);

    cudaFuncSetAttribute(gemm_f16x3_kernel,
                         cudaFuncAttributeMaxDynamicSharedMemorySize, GEMM_SMEM);
    cudaFuncSetAttribute(attn_mma_kernel,
                         cudaFuncAttributeMaxDynamicSharedMemorySize, ATTN_SMEM);

    dim3 tgrid(32, 32), tblk(32, 8);
    transpose_k<<<tgrid, tblk>>>(wq, WT + 0 * 1024 * 1024);
    transpose_k<<<tgrid, tblk>>>(wk, WT + 1 * 1024 * 1024);
    transpose_k<<<tgrid, tblk>>>(wv, WT + 2 * 1024 * 1024);
    transpose_k<<<tgrid, tblk>>>(wo, WT + 3 * 1024 * 1024);

    dim3 ggrid(Dd / 128, Mm / 128); // (8, 64)
    gemm_f16x3_kernel<<<ggrid, 256, GEMM_SMEM>>>(x, WT + 0 * 1024 * 1024, bq, Q);
    gemm_f16x3_kernel<<<ggrid, 256, GEMM_SMEM>>>(x, WT + 1 * 1024 * 1024, bk, K);
    gemm_f16x3_kernel<<<ggrid, 256, GEMM_SMEM>>>(x, WT + 2 * 1024 * 1024, bv, V);

    dim3 agrid(Nn / 128, Bb * 16); // (16, 64)
    attn_mma_kernel<<<agrid, 256, ATTN_SMEM>>>(Q, K, V, pd, O);

    gemm_f16x3_kernel<<<ggrid, 256, GEMM_SMEM>>>(O, WT + 3 * 1024 * 1024, bo, out);
}

// round 15
// speedup vs baseline: 1.3683x; 1.0300x over previous
#include <cuda_runtime.h>
#include <cuda_fp16.h>
#include <cstdint>
#include <math.h>

// Shapes fixed by dataset: x:(4,2048,1024) f32, pad:(4,2048) i32,
// w*:(1024,1024) f32, b*:(1024) f32, h=16 (depth 64). out:(4,2048,1024) f32.
static const int Bb = 4;
static const int Nn = 2048;
static const int Dd = 1024;
static const int Mm = Bb * Nn; // 8192

// Scratch (no allocs allowed).
__device__ float g_Q[8192 * 1024];
__device__ float g_K[8192 * 1024];
__device__ float g_V[8192 * 1024];
__device__ float g_O[8192 * 1024];
__device__ float g_WT[4 * 1024 * 1024];

// ---------------------------------------------------------------------------
// Helpers (sm_80-era PTX: mma.sync + ldmatrix)
// ---------------------------------------------------------------------------
__device__ __forceinline__ uint32_t smem_u32(const void* p) {
    uint32_t a;
    asm("{ .reg .u64 t; cvta.to.shared.u64 t, %1; cvt.u32.u64 %0, t; }"
        : "=r"(a) : "l"(p));
    return a;
}
__device__ __forceinline__ void ldm4(uint32_t* q, uint32_t addr) {
    asm volatile("ldmatrix.sync.aligned.m8n8.x4.shared.b16 {%0,%1,%2,%3}, [%4];"
                 : "=r"(q[0]), "=r"(q[1]), "=r"(q[2]), "=r"(q[3]) : "r"(addr));
}
__device__ __forceinline__ void ldm4t(uint32_t* q, uint32_t addr) {
    asm volatile("ldmatrix.sync.aligned.m8n8.x4.trans.shared.b16 {%0,%1,%2,%3}, [%4];"
                 : "=r"(q[0]), "=r"(q[1]), "=r"(q[2]), "=r"(q[3]) : "r"(addr));
}
// fp16 mma, fp32 accumulate. NOT volatile: ptxas may reorder independent mmas.
__device__ __forceinline__ void mma_f16(float* c, const uint32_t* a,
                                        uint32_t b0, uint32_t b1) {
    asm("mma.sync.aligned.m16n8k16.row.col.f32.f16.f16.f32 "
        "{%0,%1,%2,%3}, {%4,%5,%6,%7}, {%8,%9}, {%0,%1,%2,%3};"
        : "+f"(c[0]), "+f"(c[1]), "+f"(c[2]), "+f"(c[3])
        : "r"(a[0]), "r"(a[1]), "r"(a[2]), "r"(a[3]), "r"(b0), "r"(b1));
}
__device__ __forceinline__ uint32_t pack2h(__half a, __half b) {
    __half2 t;
    t.x = a; t.y = b;
    return *reinterpret_cast<uint32_t*>(&t);
}
// Exact split: v = hi + lo (both fp16), elementwise.
__device__ __forceinline__ void split4h(float4 v, uint2& hi, uint2& lo) {
    __half hx = __float2half_rn(v.x);
    __half hy = __float2half_rn(v.y);
    __half hz = __float2half_rn(v.z);
    __half hw = __float2half_rn(v.w);
    hi = make_uint2(pack2h(hx, hy), pack2h(hz, hw));
    lo = make_uint2(
        pack2h(__float2half_rn(v.x - __half2float(hx)),
               __float2half_rn(v.y - __half2float(hy))),
        pack2h(__float2half_rn(v.z - __half2float(hz)),
               __float2half_rn(v.w - __half2float(hw))));
}

// ---------------------------------------------------------------------------
// Fused 4x transpose: WT[z][n][k] = W_z[k][n], one launch (blockIdx.z).
// ---------------------------------------------------------------------------
__global__ __launch_bounds__(256) void transpose_k4(
    const float* __restrict__ w0, const float* __restrict__ w1,
    const float* __restrict__ w2, const float* __restrict__ w3,
    float* __restrict__ out)
{
    __shared__ float t[32][33];
    const float* in = (blockIdx.z == 0) ? w0 : (blockIdx.z == 1) ? w1
                     : (blockIdx.z == 2) ? w2 : w3;
    float* o = out + (size_t)blockIdx.z * 1024 * 1024;
    int x = blockIdx.x * 32 + threadIdx.x;
    int y = blockIdx.y * 32 + threadIdx.y;
#pragma unroll
    for (int j = 0; j < 32; j += 8)
        t[threadIdx.y + j][threadIdx.x] = in[(size_t)(y + j) * 1024 + x];
    __syncthreads();
    int xo = blockIdx.y * 32 + threadIdx.x;
    int yo = blockIdx.x * 32 + threadIdx.y;
#pragma unroll
    for (int j = 0; j < 32; j += 8)
        o[(size_t)(yo + j) * 1024 + xo] = t[threadIdx.x][threadIdx.y + j];
}

// ---------------------------------------------------------------------------
// fp16 3-term GEMM body (R14-proven: one sync per chunk, double-buffered,
// register prefetch). Shared by the fused-QKV kernel and the single kernel.
// ---------------------------------------------------------------------------
static const int PANEL = 2080;               // 128*16 + 32 pad
static const int GAHI = 0;
static const int GALO = 4 * PANEL;
static const int GBHI = 8 * PANEL;
static const int GBLO = 12 * PANEL;
static const int BUFSZ = 16 * PANEL;         // 33280
static const int GEMM_SMEM = 2 * BUFSZ;      // 66560

__device__ __forceinline__ void gemm_body(
    const float* __restrict__ A, const float* __restrict__ BT,
    const float* __restrict__ bias, float* __restrict__ C,
    int brow, int bcol, char* smem)
{
    const uint32_t sbase = smem_u32(smem);
    const int tid = threadIdx.x;
    const int wid = tid >> 5;
    const int lane = tid & 31;
    const int wm = (wid >> 1) * 32;
    const int wn = (wid & 1) * 64;

    const float* Ap = A + (size_t)brow * 1024;
    const float* Bp = BT + (size_t)bcol * 1024;

    float c[2][8][4];
#pragma unroll
    for (int mt = 0; mt < 2; ++mt)
#pragma unroll
        for (int nt = 0; nt < 8; ++nt)
#pragma unroll
            for (int i = 0; i < 4; ++i) c[mt][nt][i] = 0.0f;

    float4 ra[4], rb[4];
    auto load_chunk = [&](int kbase) {
#pragma unroll
        for (int i = 0; i < 4; ++i) {
            int id = tid + i * 256;
            int row = id >> 3, f4 = id & 7;
            ra[i] = *(const float4*)(Ap + (size_t)row * 1024 + kbase + f4 * 4);
            rb[i] = *(const float4*)(Bp + (size_t)row * 1024 + kbase + f4 * 4);
        }
    };
    auto store_chunk = [&](int buf) {
        char* bp = smem + buf * BUFSZ;
#pragma unroll
        for (int i = 0; i < 4; ++i) {
            int id = tid + i * 256;
            int row = id >> 3, f4 = id & 7;
            int off = (f4 >> 1) * PANEL + row * 16 + (f4 & 1) * 8;
            uint2 hi, lo;
            split4h(ra[i], hi, lo);
            *(uint2*)(bp + GAHI + off) = hi;
            *(uint2*)(bp + GALO + off) = lo;
            split4h(rb[i], hi, lo);
            *(uint2*)(bp + GBHI + off) = hi;
            *(uint2*)(bp + GBLO + off) = lo;
        }
    };

    load_chunk(0);
    store_chunk(0);
    __syncthreads();

    for (int ch = 0; ch < 32; ++ch) {
        const int buf = ch & 1;
        if (ch + 1 < 32) load_chunk((ch + 1) * 32);

        const uint32_t bb = sbase + buf * BUFSZ;
#pragma unroll
        for (int ks = 0; ks < 2; ++ks) {
            const int g0 = ks * 2;
            uint32_t Afh[2][4], Afl[2][4];       // [gg][quad]
            uint32_t Bfh[2][2][4], Bfl[2][2][4]; // [gg][ng][quad]
#pragma unroll
            for (int gg = 0; gg < 2; ++gg) {
                uint32_t arow = bb + (g0 + gg) * PANEL + (wm + lane) * 16;
                ldm4(Afh[gg], arow + GAHI);
                ldm4(Afl[gg], arow + GALO);
#pragma unroll
                for (int ng = 0; ng < 2; ++ng) {
                    uint32_t brow_ = bb + (g0 + gg) * PANEL +
                                     (wn + ng * 32 + lane) * 16;
                    ldm4(Bfh[gg][ng], brow_ + GBHI);
                    ldm4(Bfl[gg][ng], brow_ + GBLO);
                }
            }
            uint32_t ah[2][4], al[2][4];
#pragma unroll
            for (int mt = 0; mt < 2; ++mt) {
                ah[mt][0] = Afh[0][mt * 2]; ah[mt][1] = Afh[0][mt * 2 + 1];
                ah[mt][2] = Afh[1][mt * 2]; ah[mt][3] = Afh[1][mt * 2 + 1];
                al[mt][0] = Afl[0][mt * 2]; al[mt][1] = Afl[0][mt * 2 + 1];
                al[mt][2] = Afl[1][mt * 2]; al[mt][3] = Afl[1][mt * 2 + 1];
            }
            // term-major: 3 sweeps of 16 independent mmas
#pragma unroll
            for (int mt = 0; mt < 2; ++mt)
#pragma unroll
                for (int nt = 0; nt < 8; ++nt)
                    mma_f16(c[mt][nt], ah[mt],
                            Bfh[0][nt >> 2][nt & 3], Bfh[1][nt >> 2][nt & 3]);
#pragma unroll
            for (int mt = 0; mt < 2; ++mt)
#pragma unroll
                for (int nt = 0; nt < 8; ++nt)
                    mma_f16(c[mt][nt], ah[mt],
                            Bfl[0][nt >> 2][nt & 3], Bfl[1][nt >> 2][nt & 3]);
#pragma unroll
            for (int mt = 0; mt < 2; ++mt)
#pragma unroll
                for (int nt = 0; nt < 8; ++nt)
                    mma_f16(c[mt][nt], al[mt],
                            Bfh[0][nt >> 2][nt & 3], Bfh[1][nt >> 2][nt & 3]);
        }
        if (ch + 1 < 32) store_chunk(buf ^ 1);
        __syncthreads();
    }

    const int r0b = brow + wm + (lane >> 2);
    const int colb = bcol + wn + 2 * (lane & 3);
#pragma unroll
    for (int mt = 0; mt < 2; ++mt) {
#pragma unroll
        for (int nt = 0; nt < 8; ++nt) {
            const int col = colb + nt * 8;
            const float2 bi = *(const float2*)(bias + col);
            const int r0 = r0b + mt * 16;
            float2 v0 = make_float2(c[mt][nt][0] + bi.x, c[mt][nt][1] + bi.y);
            float2 v1 = make_float2(c[mt][nt][2] + bi.x, c[mt][nt][3] + bi.y);
            *(float2*)(C + (size_t)r0 * 1024 + col) = v0;
            *(float2*)(C + (size_t)(r0 + 8) * 1024 + col) = v1;
        }
    }
}

// Fused QKV: one launch, grid (24, 64). blockIdx.x>>3 selects weight/out.
// Merges the 3 partial-wave tails of the separate launches into one.
__global__ __launch_bounds__(256) void gemm_qkv_kernel(
    const float* __restrict__ x, const float* __restrict__ WT,
    const float* __restrict__ bq, const float* __restrict__ bk,
    const float* __restrict__ bv,
    float* __restrict__ Q, float* __restrict__ K, float* __restrict__ V)
{
    extern __shared__ __align__(16) char smem[];
    const int w = blockIdx.x >> 3;
    const float* bias = (w == 0) ? bq : (w == 1) ? bk : bv;
    float* C = (w == 0) ? Q : (w == 1) ? K : V;
    gemm_body(x, WT + (size_t)w * 1048576, bias, C,
              blockIdx.y * 128, (blockIdx.x & 7) * 128, smem);
}

// Single GEMM (output projection).
__global__ __launch_bounds__(256) void gemm_f16x3_kernel(
    const float* __restrict__ A, const float* __restrict__ BT,
    const float* __restrict__ bias, float* __restrict__ C)
{
    extern __shared__ __align__(16) char smem[];
    gemm_body(A, BT, bias, C, blockIdx.y * 128, blockIdx.x * 128, smem);
}

// ---------------------------------------------------------------------------
// Tensor-core flash attention, fp16 3-term (R14: double-buffered K/V +
// register prefetch, one sync per tile). Unchanged.
// ---------------------------------------------------------------------------
static const int QPNL = 2080;                 // 128 rows * 16B + pad
static const int KPNL = 1056;                 // 64 rows * 16B + pad
static const int VSTR = 144;                  // 128B row + 16 pad
static const int SQHI = 0;
static const int SQLO = 8 * QPNL;             // 16640
static const int SBUF0 = 16 * QPNL;           // 33280
// per-buffer layout
static const int AKHI = 0;
static const int AKLO = 8 * KPNL;             // 8448
static const int AVHI = 16 * KPNL;            // 16896
static const int AVLO = AVHI + 64 * VSTR;     // 26112
static const int AMSK = AVLO + 64 * VSTR;     // 35328
static const int BUFSTR = AMSK + 64 * 4;      // 35584
static const int ATTN_SMEM = SBUF0 + 2 * BUFSTR; // 104448

__global__ __launch_bounds__(256) void attn_mma_kernel(
    const float* __restrict__ Q, const float* __restrict__ K,
    const float* __restrict__ V, const int* __restrict__ pad,
    float* __restrict__ O)
{
    extern __shared__ __align__(16) char smem[];
    const uint32_t sb = smem_u32(smem);
    const int tid = threadIdx.x;
    const int wid = tid >> 5;
    const int lane = tid & 31;
    const int wm = wid * 16;
    const int bh = blockIdx.y;
    const int b = bh >> 4;
    const int h = bh & 15;
    const int qbase = blockIdx.x * 128;

    // ---- stage Q tile (x 1/8) into hi/lo fp16 panels ----
#pragma unroll
    for (int i = 0; i < 8; ++i) {
        int id = tid + i * 256;
        int row = id >> 4, f4 = id & 15;
        float4 v = *(const float4*)(Q + ((size_t)(b * Nn + qbase + row)) * Dd +
                                    h * 64 + f4 * 4);
        v.x *= 0.125f; v.y *= 0.125f; v.z *= 0.125f; v.w *= 0.125f;
        uint2 hi, lo;
        split4h(v, hi, lo);
        int off = (f4 >> 1) * QPNL + row * 16 + (f4 & 1) * 8;
        *(uint2*)(smem + SQHI + off) = hi;
        *(uint2*)(smem + SQLO + off) = lo;
    }

    // ---- K/V register prefetch + split/store machinery ----
    float4 rk[4], rv[4];
    auto load_kv = [&](int kt) {
#pragma unroll
        for (int i = 0; i < 4; ++i) {
            int id = tid + i * 256;
            int row = id >> 4, f4 = id & 15;
            size_t g = ((size_t)(b * Nn + kt + row)) * Dd + h * 64 + f4 * 4;
            rk[i] = *(const float4*)(K + g);
            rv[i] = *(const float4*)(V + g);
        }
    };
    auto store_kv = [&](int buf) {
        char* bp = smem + SBUF0 + buf * BUFSTR;
#pragma unroll
        for (int i = 0; i < 4; ++i) {
            int id = tid + i * 256;
            int row = id >> 4, f4 = id & 15;
            uint2 hi, lo;
            split4h(rk[i], hi, lo);
            int koff = (f4 >> 1) * KPNL + row * 16 + (f4 & 1) * 8;
            *(uint2*)(bp + AKHI + koff) = hi;
            *(uint2*)(bp + AKLO + koff) = lo;
            split4h(rv[i], hi, lo);
            int voff = row * VSTR + f4 * 8;
            *(uint2*)(bp + AVHI + voff) = hi;
            *(uint2*)(bp + AVLO + voff) = lo;
        }
    };
    auto store_mask = [&](int buf, int kt) {
        if (tid < 64)
            *(float*)(smem + SBUF0 + buf * BUFSTR + AMSK + tid * 4) =
                (pad[b * Nn + kt + tid] == 0) ? 1.0f : 0.0f;
    };

    load_kv(0);
    store_kv(0);
    store_mask(0, 0);
    __syncthreads();

    // ---- Q fragments to registers ----
    uint32_t qh[4][4], ql[4][4];
#pragma unroll
    for (int kc = 0; kc < 4; ++kc) {
        uint32_t addr = sb + SQHI + (2 * kc + (lane >> 4)) * QPNL +
                        (wm + (lane & 15)) * 16;
        ldm4(qh[kc], addr);
        ldm4(ql[kc], addr + (SQLO - SQHI));
    }

    const int r = lane >> 2;
    const int qn0 = qbase + wm + r;
    const int qn1 = qn0 + 8;
    const float vn0 = (pad[b * Nn + qn0] == 0) ? 1.0f : 0.0f;
    const float vn1 = (pad[b * Nn + qn1] == 0) ? 1.0f : 0.0f;

    float o[8][4];
#pragma unroll
    for (int nd = 0; nd < 8; ++nd)
#pragma unroll
        for (int i = 0; i < 4; ++i) o[nd][i] = 0.0f;
    float m0 = -1e30f, m1 = -1e30f, l0 = 0.0f, l1 = 0.0f;

    for (int t = 0; t < 32; ++t) {
        const int buf = t & 1;
        if (t + 1 < 32) load_kv((t + 1) * 64);   // prefetch: overlapped w/ mma

        const uint32_t kb = sb + SBUF0 + buf * BUFSTR;
        const char* mp = smem + SBUF0 + buf * BUFSTR + AMSK;

        // ---- S = qh Kh + qh Kl + ql Kh ----
        float s[8][4];
#pragma unroll
        for (int nt = 0; nt < 8; ++nt)
#pragma unroll
            for (int i = 0; i < 4; ++i) s[nt][i] = 0.0f;

#pragma unroll
        for (int kc = 0; kc < 4; ++kc) {
            uint32_t b0h[4], b4h[4], b1h[4], b5h[4];
            uint32_t b0l[4], b4l[4], b1l[4], b5l[4];
            uint32_t p0 = kb + AKHI + (2 * kc) * KPNL + lane * 16;
            uint32_t p1 = p0 + KPNL;
            ldm4(b0h, p0);
            ldm4(b4h, p0 + 32 * 16);
            ldm4(b1h, p1);
            ldm4(b5h, p1 + 32 * 16);
            ldm4(b0l, p0 + (AKLO - AKHI));
            ldm4(b4l, p0 + 32 * 16 + (AKLO - AKHI));
            ldm4(b1l, p1 + (AKLO - AKHI));
            ldm4(b5l, p1 + 32 * 16 + (AKLO - AKHI));
#pragma unroll
            for (int nt = 0; nt < 8; ++nt)
                mma_f16(s[nt], qh[kc],
                        (nt < 4) ? b0h[nt] : b4h[nt - 4],
                        (nt < 4) ? b1h[nt] : b5h[nt - 4]);
#pragma unroll
            for (int nt = 0; nt < 8; ++nt)
                mma_f16(s[nt], qh[kc],
                        (nt < 4) ? b0l[nt] : b4l[nt - 4],
                        (nt < 4) ? b1l[nt] : b5l[nt - 4]);
#pragma unroll
            for (int nt = 0; nt < 8; ++nt)
                mma_f16(s[nt], ql[kc],
                        (nt < 4) ? b0h[nt] : b4h[nt - 4],
                        (nt < 4) ? b1h[nt] : b5h[nt - 4]);
        }

        // ---- mask (exact-zero form) + online softmax ----
        float tm0 = -1e30f, tm1 = -1e30f;
#pragma unroll
        for (int nt = 0; nt < 8; ++nt) {
            float2 vm = *(const float2*)(mp + (nt * 8 + 2 * (lane & 3)) * 4);
            s[nt][0] = fmaf(1.0f - vn0 * vm.x, -1e6f, s[nt][0]);
            s[nt][1] = fmaf(1.0f - vn0 * vm.y, -1e6f, s[nt][1]);
            s[nt][2] = fmaf(1.0f - vn1 * vm.x, -1e6f, s[nt][2]);
            s[nt][3] = fmaf(1.0f - vn1 * vm.y, -1e6f, s[nt][3]);
            tm0 = fmaxf(tm0, fmaxf(s[nt][0], s[nt][1]));
            tm1 = fmaxf(tm1, fmaxf(s[nt][2], s[nt][3]));
        }
        tm0 = fmaxf(tm0, __shfl_xor_sync(0xffffffffu, tm0, 1));
        tm0 = fmaxf(tm0, __shfl_xor_sync(0xffffffffu, tm0, 2));
        tm1 = fmaxf(tm1, __shfl_xor_sync(0xffffffffu, tm1, 1));
        tm1 = fmaxf(tm1, __shfl_xor_sync(0xffffffffu, tm1, 2));

        float m0n = fmaxf(m0, tm0), m1n = fmaxf(m1, tm1);
        float a0 = __expf(m0 - m0n), a1 = __expf(m1 - m1n);
        m0 = m0n; m1 = m1n;

        float sum0 = 0.0f, sum1 = 0.0f;
#pragma unroll
        for (int nt = 0; nt < 8; ++nt) {
            s[nt][0] = __expf(s[nt][0] - m0);
            s[nt][1] = __expf(s[nt][1] - m0);
            s[nt][2] = __expf(s[nt][2] - m1);
            s[nt][3] = __expf(s[nt][3] - m1);
            sum0 += s[nt][0] + s[nt][1];
            sum1 += s[nt][2] + s[nt][3];
        }
        sum0 += __shfl_xor_sync(0xffffffffu, sum0, 1);
        sum0 += __shfl_xor_sync(0xffffffffu, sum0, 2);
        sum1 += __shfl_xor_sync(0xffffffffu, sum1, 1);
        sum1 += __shfl_xor_sync(0xffffffffu, sum1, 2);
        l0 = l0 * a0 + sum0;
        l1 = l1 * a1 + sum1;
#pragma unroll
        for (int nd = 0; nd < 8; ++nd) {
            o[nd][0] *= a0; o[nd][1] *= a0;
            o[nd][2] *= a1; o[nd][3] *= a1;
        }

        // ---- O += Ph Vh + Ph Vl + Pl Vh ----
#pragma unroll
        for (int kc = 0; kc < 4; ++kc) {
            uint32_t ph[4], pl[4];
            {
                const float* pa = s[2 * kc];
                const float* pb = s[2 * kc + 1];
                __half h0 = __float2half_rn(pa[0]);
                __half h1 = __float2half_rn(pa[1]);
                __half h2 = __float2half_rn(pa[2]);
                __half h3 = __float2half_rn(pa[3]);
                __half h4 = __float2half_rn(pb[0]);
                __half h5 = __float2half_rn(pb[1]);
                __half h6 = __float2half_rn(pb[2]);
                __half h7 = __float2half_rn(pb[3]);
                ph[0] = pack2h(h0, h1);
                ph[1] = pack2h(h2, h3);
                ph[2] = pack2h(h4, h5);
                ph[3] = pack2h(h6, h7);
                pl[0] = pack2h(__float2half_rn(pa[0] - __half2float(h0)),
                               __float2half_rn(pa[1] - __half2float(h1)));
                pl[1] = pack2h(__float2half_rn(pa[2] - __half2float(h2)),
                               __float2half_rn(pa[3] - __half2float(h3)));
                pl[2] = pack2h(__float2half_rn(pb[0] - __half2float(h4)),
                               __float2half_rn(pb[1] - __half2float(h5)));
                pl[3] = pack2h(__float2half_rn(pb[2] - __half2float(h6)),
                               __float2half_rn(pb[3] - __half2float(h7)));
            }
            uint32_t vh[4][4], vl[4][4];
#pragma unroll
            for (int jj = 0; jj < 4; ++jj) {
                uint32_t va = kb + AVHI + (kc * 16 + (lane & 15)) * VSTR +
                              (2 * jj + (lane >> 4)) * 16;
                ldm4t(vh[jj], va);
                ldm4t(vl[jj], va + (AVLO - AVHI));
            }
#pragma unroll
            for (int jj = 0; jj < 4; ++jj) {
                mma_f16(o[2 * jj], ph, vh[jj][0], vh[jj][1]);
                mma_f16(o[2 * jj + 1], ph, vh[jj][2], vh[jj][3]);
            }
#pragma unroll
            for (int jj = 0; jj < 4; ++jj) {
                mma_f16(o[2 * jj], ph, vl[jj][0], vl[jj][1]);
                mma_f16(o[2 * jj + 1], ph, vl[jj][2], vl[jj][3]);
            }
#pragma unroll
            for (int jj = 0; jj < 4; ++jj) {
                mma_f16(o[2 * jj], pl, vh[jj][0], vh[jj][1]);
                mma_f16(o[2 * jj + 1], pl, vh[jj][2], vh[jj][3]);
            }
        }

        if (t + 1 < 32) {
            store_kv(buf ^ 1);
            store_mask(buf ^ 1, (t + 1) * 64);
        }
        __syncthreads();
    }

    // ---- epilogue ----
    const float inv0 = 1.0f / l0, inv1 = 1.0f / l1;
    const size_t row0 = (size_t)(b * Nn + qn0) * Dd;
    const size_t row1 = (size_t)(b * Nn + qn1) * Dd;
#pragma unroll
    for (int nd = 0; nd < 8; ++nd) {
        const int col = h * 64 + nd * 8 + 2 * (lane & 3);
        *(float2*)(O + row0 + col) =
            make_float2(o[nd][0] * inv0, o[nd][1] * inv0);
        *(float2*)(O + row1 + col) =
            make_float2(o[nd][2] * inv1, o[nd][3] * inv1);
    }
}

// ---------------------------------------------------------------------------
// Launch
// ---------------------------------------------------------------------------
extern "C" void kernel_launch(void* const* d_in, const int* in_sizes, int n_in,
                              void* d_out, int out_size)
{
    const float* x  = (const float*)d_in[0];
    const int*   pd = (const int*)d_in[1];
    const float* wq = (const float*)d_in[2];
    const float* bq = (const float*)d_in[3];
    const float* wk = (const float*)d_in[4];
    const float* bk = (const float*)d_in[5];
    const float* wv = (const float*)d_in[6];
    const float* bv = (const float*)d_in[7];
    const float* wo = (const float*)d_in[8];
    const float* bo = (const float*)d_in[9];
    float* out = (float*)d_out;

    float *Q, *K, *V, *O, *WT;
    cudaGetSymbolAddress((void**)&Q, g_Q);
    cudaGetSymbolAddress((void**)&K, g_K);
    cudaGetSymbolAddress((void**)&V, g_V);
    cudaGetSymbolAddress((void**)&O, g_O);
    cudaGetSymbolAddress((void**)&WT, g_WT);

    cudaFuncSetAttribute(gemm_qkv_kernel,
                         cudaFuncAttributeMaxDynamicSharedMemorySize, GEMM_SMEM);
    cudaFuncSetAttribute(gemm_f16x3_kernel,
                         cudaFuncAttributeMaxDynamicSharedMemorySize, GEMM_SMEM);
    cudaFuncSetAttribute(attn_mma_kernel,
                         cudaFuncAttributeMaxDynamicSharedMemorySize, ATTN_SMEM);

    // One fused launch: 4 weight transposes.
    dim3 tgrid(32, 32, 4), tblk(32, 8);
    transpose_k4<<<tgrid, tblk>>>(wq, wk, wv, wo, WT);

    // One fused launch: Q, K, V projections (merges 3 partial-wave tails).
    dim3 qkvgrid(24, 64);
    gemm_qkv_kernel<<<qkvgrid, 256, GEMM_SMEM>>>(x, WT, bq, bk, bv, Q, K, V);

    dim3 agrid(Nn / 128, Bb * 16); // (16, 64)
    attn_mma_kernel<<<agrid, 256, ATTN_SMEM>>>(Q, K, V, pd, O);

    dim3 ggrid(Dd / 128, Mm / 128); // (8, 64)
    gemm_f16x3_kernel<<<ggrid, 256, GEMM_SMEM>>>(O, WT + 3 * 1024 * 1024, bo, out);
}